// round 4
// baseline (speedup 1.0000x reference)
#include <cuda_runtime.h>
#include <math.h>
#include <float.h>

// Problem sizes
constexpr int NB = 32768;   // batch
constexpr int ND = 256;     // dim
constexpr int NK = 8192;    // codes
constexpr float DECAY = 0.99f;
constexpr float EPSV  = 1e-5f;
constexpr float CCOST = 0.25f;

// Output layout (flattened reference tuple, float32):
// z_q_st [B*D] | loss [1] | indices [B] | perplexity [1] | new_embedding [K*D] | new_ema_cs [K] | new_ema_es [K*D]
constexpr size_t O_ZQ   = 0;
constexpr size_t O_LOSS = (size_t)NB * ND;            // 8388608
constexpr size_t O_IDX  = O_LOSS + 1;                 // 8388609
constexpr size_t O_PLX  = O_IDX + NB;                 // 8421377
constexpr size_t O_EMB  = O_PLX + 1;                  // 8421378  (== 2 mod 4 -> only 8B aligned!)
constexpr size_t O_CS   = O_EMB + (size_t)NK * ND;    // 10518530
constexpr size_t O_ES   = O_CS + NK;                  // 10526722 (== 2 mod 4 -> only 8B aligned!)

// Scratch (device globals — no allocation)
__device__ float g_enorm[NK];
__device__ int   g_idx[NB];
__device__ float g_cs[NK];                  // cluster_size counts
__device__ float g_esum[(size_t)NK * ND];   // segment sum of z
__device__ float g_newcs[NK];               // pre-dead new_ema_cs
__device__ float g_loss;
__device__ float g_n;
__device__ float g_plx;

// ---------------------------------------------------------------------------
__global__ void k_zero() {
    int i = blockIdx.x * blockDim.x + threadIdx.x;
    int stride = gridDim.x * blockDim.x;
    for (size_t j = i; j < (size_t)NK * ND; j += stride) g_esum[j] = 0.f;
    for (int j = i; j < NK; j += stride) g_cs[j] = 0.f;
    if (i == 0) { g_loss = 0.f; g_n = 0.f; g_plx = 0.f; }
}

// ---------------------------------------------------------------------------
// e_norm2[k] = sum_d e[k][d]^2 ; one warp per code.
__global__ void k_enorm(const float* __restrict__ emb) {
    int warp = threadIdx.x >> 5, lane = threadIdx.x & 31;
    int k = blockIdx.x * 8 + warp;
    const float4* ep = (const float4*)(emb + (size_t)k * ND) + lane * 2;
    float4 a = ep[0], b = ep[1];
    float s = a.x*a.x + a.y*a.y + a.z*a.z + a.w*a.w
            + b.x*b.x + b.y*b.y + b.z*b.z + b.w*b.w;
    #pragma unroll
    for (int o = 16; o > 0; o >>= 1) s += __shfl_xor_sync(0xffffffffu, s, o);
    if (lane == 0) g_enorm[k] = s;
}

// ---------------------------------------------------------------------------
// Fused distance + argmin: per block, TM=64 rows of z vs all K codes.
// dist = e_norm2[k] - 2 * dot(z_b, e_k)  (z^2 term constant per row).
constexpr int TM = 64;
constexpr int TN = 64;
constexpr int DC = 32;

__global__ __launch_bounds__(256, 2)
void k_argmin(const float* __restrict__ z, const float* __restrict__ emb) {
    extern __shared__ float sm[];
    float* zs   = sm;                       // [256][64] transposed z tile
    float* es   = sm + ND * TM;             // [32][64]  transposed e chunk
    float* redv = es + DC * TN;             // [64][16]
    int*   redi = (int*)(redv + TM * 16);   // [64][16]

    const int tid = threadIdx.x;
    const int tx = tid & 15, ty = tid >> 4;
    const int b0 = blockIdx.x * TM;

    // Load z tile transposed: zs[d][r]
    {
        int r = tid >> 2;      // 0..63
        int dg = tid & 3;      // 0..3
        const float4* zp = (const float4*)(z + (size_t)(b0 + r) * ND);
        #pragma unroll 4
        for (int d = dg * 64; d < dg * 64 + 64; d += 4) {
            float4 v = zp[d >> 2];
            zs[(d + 0) * TM + r] = v.x;
            zs[(d + 1) * TM + r] = v.y;
            zs[(d + 2) * TM + r] = v.z;
            zs[(d + 3) * TM + r] = v.w;
        }
    }

    float bestv[4];
    int   besti[4];
    #pragma unroll
    for (int i = 0; i < 4; i++) { bestv[i] = FLT_MAX; besti[i] = 0x7fffffff; }

    for (int k0 = 0; k0 < NK; k0 += TN) {
        float acc[4][4] = {};
        for (int d0 = 0; d0 < ND; d0 += DC) {
            __syncthreads();
            {   // load es[dd][n] = e[k0+n][d0+dd]
                int n = tid >> 2;      // 0..63
                int dg = tid & 3;      // 0..3 -> dd = dg*8 .. +7
                const float4* ep =
                    (const float4*)(emb + (size_t)(k0 + n) * ND + d0 + dg * 8);
                float4 a = ep[0], b = ep[1];
                int db = dg * 8;
                es[(db + 0) * TN + n] = a.x;
                es[(db + 1) * TN + n] = a.y;
                es[(db + 2) * TN + n] = a.z;
                es[(db + 3) * TN + n] = a.w;
                es[(db + 4) * TN + n] = b.x;
                es[(db + 5) * TN + n] = b.y;
                es[(db + 6) * TN + n] = b.z;
                es[(db + 7) * TN + n] = b.w;
            }
            __syncthreads();
            #pragma unroll
            for (int dd = 0; dd < DC; dd++) {
                float4 az = *(const float4*)&zs[(d0 + dd) * TM + ty * 4];
                float4 ae = *(const float4*)&es[dd * TN + tx * 4];
                acc[0][0] += az.x * ae.x; acc[0][1] += az.x * ae.y;
                acc[0][2] += az.x * ae.z; acc[0][3] += az.x * ae.w;
                acc[1][0] += az.y * ae.x; acc[1][1] += az.y * ae.y;
                acc[1][2] += az.y * ae.z; acc[1][3] += az.y * ae.w;
                acc[2][0] += az.z * ae.x; acc[2][1] += az.z * ae.y;
                acc[2][2] += az.z * ae.z; acc[2][3] += az.z * ae.w;
                acc[3][0] += az.w * ae.x; acc[3][1] += az.w * ae.y;
                acc[3][2] += az.w * ae.z; acc[3][3] += az.w * ae.w;
            }
        }
        #pragma unroll
        for (int j = 0; j < 4; j++) {
            int k = k0 + tx * 4 + j;
            float en = __ldg(&g_enorm[k]);
            #pragma unroll
            for (int i = 0; i < 4; i++) {
                float dist = en - 2.f * acc[i][j];
                if (dist < bestv[i]) { bestv[i] = dist; besti[i] = k; }
            }
        }
    }
    __syncthreads();
    #pragma unroll
    for (int i = 0; i < 4; i++) {
        redv[(ty * 4 + i) * 16 + tx] = bestv[i];
        redi[(ty * 4 + i) * 16 + tx] = besti[i];
    }
    __syncthreads();
    if (tid < TM) {
        float bv = redv[tid * 16]; int bi = redi[tid * 16];
        #pragma unroll
        for (int t = 1; t < 16; t++) {
            float v = redv[tid * 16 + t]; int ii = redi[tid * 16 + t];
            if (v < bv || (v == bv && ii < bi)) { bv = v; bi = ii; }
        }
        g_idx[b0 + tid] = bi;
    }
}

// ---------------------------------------------------------------------------
// Per-row: gather z_q -> out, loss accum, cluster_size++, segment-sum of z.
// One warp per row, 8 rows per block.
__global__ void k_scatter(const float* __restrict__ z,
                          const float* __restrict__ emb,
                          float* __restrict__ out) {
    __shared__ float ls[8];
    int warp = threadIdx.x >> 5, lane = threadIdx.x & 31;
    int b = blockIdx.x * 8 + warp;
    int idx = g_idx[b];
    const float4* zp = (const float4*)(z + (size_t)b * ND);
    const float4* ep = (const float4*)(emb + (size_t)idx * ND);
    float4* oq = (float4*)(out + O_ZQ + (size_t)b * ND);
    float* esum = g_esum + (size_t)idx * ND;
    float lsum = 0.f;
    #pragma unroll
    for (int j = lane; j < ND / 4; j += 32) {
        float4 zv = zp[j], ev = ep[j];
        oq[j] = ev;
        float dx = ev.x - zv.x, dy = ev.y - zv.y, dz = ev.z - zv.z, dw = ev.w - zv.w;
        lsum += dx * dx + dy * dy + dz * dz + dw * dw;
        atomicAdd(&esum[j * 4 + 0], zv.x);
        atomicAdd(&esum[j * 4 + 1], zv.y);
        atomicAdd(&esum[j * 4 + 2], zv.z);
        atomicAdd(&esum[j * 4 + 3], zv.w);
    }
    #pragma unroll
    for (int o = 16; o > 0; o >>= 1) lsum += __shfl_xor_sync(0xffffffffu, lsum, o);
    if (lane == 0) {
        ls[warp] = lsum;
        atomicAdd(&g_cs[idx], 1.f);
        out[O_IDX + b] = (float)idx;
    }
    __syncthreads();
    if (threadIdx.x == 0) {
        float s = 0.f;
        #pragma unroll
        for (int w = 0; w < 8; w++) s += ls[w];
        atomicAdd(&g_loss, s);
    }
}

// ---------------------------------------------------------------------------
// new_ema_cs (pre-dead), n = sum, perplexity accumulation.
__global__ void k_ema(const float* __restrict__ ema_cs) {
    __shared__ float sn[8], sp[8];
    int k = blockIdx.x * 256 + threadIdx.x;
    float cs = g_cs[k];
    float ncs = DECAY * ema_cs[k] + (1.f - DECAY) * cs;
    g_newcs[k] = ncs;
    float p = cs * (1.f / NB);
    float t = p * logf(p + 1e-10f);
    #pragma unroll
    for (int o = 16; o > 0; o >>= 1) {
        ncs += __shfl_xor_sync(0xffffffffu, ncs, o);
        t   += __shfl_xor_sync(0xffffffffu, t, o);
    }
    int warp = threadIdx.x >> 5, lane = threadIdx.x & 31;
    if (lane == 0) { sn[warp] = ncs; sp[warp] = t; }
    __syncthreads();
    if (threadIdx.x == 0) {
        float a = 0.f, b = 0.f;
        #pragma unroll
        for (int w = 0; w < 8; w++) { a += sn[w]; b += sp[w]; }
        atomicAdd(&g_n, a);
        atomicAdd(&g_plx, b);
    }
}

// ---------------------------------------------------------------------------
// Finalize codebook rows: smoothing, new_embedding, dead-code reinit; write out.
// 4 codes per block of 256 threads (64 threads = one 256-float code row).
// NOTE: out+O_EMB and out+O_ES are only 8-byte aligned (offsets == 2 mod 4
// floats), so stores there MUST be float2, not float4.
__global__ void k_final(const float* __restrict__ z,
                        const float* __restrict__ ema_es,
                        const float* __restrict__ noise,
                        const int* __restrict__ reinit_idx,
                        float* __restrict__ out) {
    int k = blockIdx.x * 4 + (threadIdx.x >> 6);
    int dq = threadIdx.x & 63;   // float4 chunk index within the row
    float n = g_n;
    float ncs = g_newcs[k];
    float cs_sm = (ncs + EPSV) / (n + NK * EPSV) * n;
    bool dead = (ncs / n) < (1.f / NK / 10.f);
    int ridx = reinit_idx[k];

    float4 eo = ((const float4*)(ema_es + (size_t)k * ND))[dq];
    float4 s  = ((const float4*)(g_esum + (size_t)k * ND))[dq];
    float4 nes;
    nes.x = DECAY * eo.x + (1.f - DECAY) * s.x;
    nes.y = DECAY * eo.y + (1.f - DECAY) * s.y;
    nes.z = DECAY * eo.z + (1.f - DECAY) * s.z;
    nes.w = DECAY * eo.w + (1.f - DECAY) * s.w;
    float inv = 1.f / cs_sm;
    float4 nemb = make_float4(nes.x * inv, nes.y * inv, nes.z * inv, nes.w * inv);
    if (dead) {
        float4 zr = ((const float4*)(z + (size_t)ridx * ND))[dq];
        float4 nz = ((const float4*)(noise + (size_t)k * ND))[dq];
        float4 ri = make_float4(zr.x + nz.x, zr.y + nz.y, zr.z + nz.z, zr.w + nz.w);
        nemb = ri;
        nes = ri;
    }
    // 8B-aligned stores (float2) for the misaligned output regions
    float2* oemb = (float2*)(out + O_EMB + (size_t)k * ND) + dq * 2;
    float2* oes  = (float2*)(out + O_ES  + (size_t)k * ND) + dq * 2;
    oemb[0] = make_float2(nemb.x, nemb.y);
    oemb[1] = make_float2(nemb.z, nemb.w);
    oes[0]  = make_float2(nes.x, nes.y);
    oes[1]  = make_float2(nes.z, nes.w);
    if (dq == 0) out[O_CS + k] = dead ? 1.f : ncs;
}

// ---------------------------------------------------------------------------
__global__ void k_scalars(float* __restrict__ out) {
    out[O_LOSS] = CCOST * g_loss / ((float)NB * (float)ND);
    out[O_PLX]  = expf(-g_plx);
}

// ---------------------------------------------------------------------------
extern "C" void kernel_launch(void* const* d_in, const int* in_sizes, int n_in,
                              void* d_out, int out_size) {
    const float* z        = (const float*)d_in[0];
    const float* emb      = (const float*)d_in[1];
    const float* ema_cs   = (const float*)d_in[2];
    const float* ema_es   = (const float*)d_in[3];
    const float* noise    = (const float*)d_in[4];
    const int*   ridx     = (const int*)d_in[5];
    float* out = (float*)d_out;

    static bool attr_set = false;
    if (!attr_set) {
        cudaFuncSetAttribute(k_argmin, cudaFuncAttributeMaxDynamicSharedMemorySize,
                             (ND * TM + DC * TN + TM * 16 * 2) * 4);
        attr_set = true;
    }

    k_zero<<<1024, 256>>>();
    k_enorm<<<NK / 8, 256>>>(emb);
    size_t smem = (size_t)(ND * TM + DC * TN + TM * 16 * 2) * 4;  // 80 KB
    k_argmin<<<NB / TM, 256, smem>>>(z, emb);
    k_scatter<<<NB / 8, 256>>>(z, emb, out);
    k_ema<<<NK / 256, 256>>>(ema_cs);
    k_final<<<NK / 4, 256>>>(z, ema_es, noise, ridx, out);
    k_scalars<<<1, 1>>>(out);
}

// round 5
// speedup vs baseline: 1.2668x; 1.2668x over previous
#include <cuda_runtime.h>
#include <math.h>
#include <float.h>

// Problem sizes
constexpr int NB = 32768;   // batch
constexpr int ND = 256;     // dim
constexpr int NK = 8192;    // codes
constexpr float DECAY = 0.99f;
constexpr float EPSV  = 1e-5f;
constexpr float CCOST = 0.25f;

// Output layout (flattened reference tuple, float32):
// z_q_st [B*D] | loss [1] | indices [B] | perplexity [1] | new_embedding [K*D] | new_ema_cs [K] | new_ema_es [K*D]
constexpr size_t O_ZQ   = 0;
constexpr size_t O_LOSS = (size_t)NB * ND;            // 8388608
constexpr size_t O_IDX  = O_LOSS + 1;                 // 8388609
constexpr size_t O_PLX  = O_IDX + NB;                 // 8421377
constexpr size_t O_EMB  = O_PLX + 1;                  // 8421378  (== 2 mod 4 -> only 8B aligned!)
constexpr size_t O_CS   = O_EMB + (size_t)NK * ND;    // 10518530
constexpr size_t O_ES   = O_CS + NK;                  // 10526722 (== 2 mod 4 -> only 8B aligned!)

// Scratch (device globals — no allocation)
__device__ float g_enorm[NK];
__device__ int   g_idx[NB];
__device__ float g_cs[NK];                  // cluster_size counts
__device__ float g_esum[(size_t)NK * ND];   // segment sum of z
__device__ float g_newcs[NK];               // pre-dead new_ema_cs
__device__ float g_loss;
__device__ float g_n;
__device__ float g_plx;

// ---------------------------------------------------------------------------
__global__ void k_zero() {
    int i = blockIdx.x * blockDim.x + threadIdx.x;
    int stride = gridDim.x * blockDim.x;
    for (size_t j = i; j < (size_t)NK * ND; j += stride) g_esum[j] = 0.f;
    for (int j = i; j < NK; j += stride) g_cs[j] = 0.f;
    if (i == 0) { g_loss = 0.f; g_n = 0.f; g_plx = 0.f; }
}

// ---------------------------------------------------------------------------
// e_norm2[k] = sum_d e[k][d]^2 ; one warp per code.
__global__ void k_enorm(const float* __restrict__ emb) {
    int warp = threadIdx.x >> 5, lane = threadIdx.x & 31;
    int k = blockIdx.x * 8 + warp;
    const float4* ep = (const float4*)(emb + (size_t)k * ND) + lane * 2;
    float4 a = ep[0], b = ep[1];
    float s = a.x*a.x + a.y*a.y + a.z*a.z + a.w*a.w
            + b.x*b.x + b.y*b.y + b.z*b.z + b.w*b.w;
    #pragma unroll
    for (int o = 16; o > 0; o >>= 1) s += __shfl_xor_sync(0xffffffffu, s, o);
    if (lane == 0) g_enorm[k] = s;
}

// ---------------------------------------------------------------------------
// Fused distance + argmin with packed f32x2 FMA (FFMA2 — full fp32 rate on
// Blackwell; scalar FFMA runs at half rate).
// Tile: TM=64 rows of z x TN=128 codes per k-step. 256 threads as 8x32:
//   ty = tid>>5 (0..7)  -> 8 rows each (row-pairs packed in b64)
//   tx = tid&31 (0..31) -> 4 cols each
// dist = e_norm2[k] - 2 * dot(z_b, e_k)  (z^2 term constant per row).
constexpr int TM = 64;
constexpr int TN = 128;
constexpr int DC = 32;

__device__ __forceinline__ void fma2(unsigned long long& acc,
                                     unsigned long long a,
                                     unsigned long long b) {
    asm("fma.rn.f32x2 %0, %1, %2, %0;" : "+l"(acc) : "l"(a), "l"(b));
}
__device__ __forceinline__ unsigned long long dup2(float v) {
    unsigned long long d;
    unsigned int r = __float_as_uint(v);
    asm("mov.b64 %0, {%1, %1};" : "=l"(d) : "r"(r));
    return d;
}

__global__ __launch_bounds__(256, 2)
void k_argmin(const float* __restrict__ z, const float* __restrict__ emb) {
    extern __shared__ float sm[];
    float* zs = sm;             // [256][64]  transposed z tile (resident)
    float* es = sm + ND * TM;   // [32][128]  transposed e chunk

    const int tid = threadIdx.x;
    const int tx = tid & 31, ty = tid >> 5;
    const int b0 = blockIdx.x * TM;

    // Load z tile transposed: zs[d][r]
    {
        int r = tid >> 2;      // 0..63
        int dg = tid & 3;      // 0..3
        const float4* zp = (const float4*)(z + (size_t)(b0 + r) * ND);
        #pragma unroll 4
        for (int d = dg * 64; d < dg * 64 + 64; d += 4) {
            float4 v = zp[d >> 2];
            zs[(d + 0) * TM + r] = v.x;
            zs[(d + 1) * TM + r] = v.y;
            zs[(d + 2) * TM + r] = v.z;
            zs[(d + 3) * TM + r] = v.w;
        }
    }

    float bestv[8];
    int   besti[8];
    #pragma unroll
    for (int i = 0; i < 8; i++) { bestv[i] = FLT_MAX; besti[i] = 0x7fffffff; }

    for (int k0 = 0; k0 < NK; k0 += TN) {
        unsigned long long acc[4][4];  // [j][row-pair]
        #pragma unroll
        for (int j = 0; j < 4; j++)
            #pragma unroll
            for (int rp = 0; rp < 4; rp++) acc[j][rp] = 0ull;

        for (int d0 = 0; d0 < ND; d0 += DC) {
            __syncthreads();
            {   // load es[dd][n] = e[k0+n][d0+dd]; n 0..127, dd 0..31
                int n = tid >> 1;        // 0..127
                int dg = tid & 1;        // 0..1 -> dd base 0 or 16
                const float4* ep =
                    (const float4*)(emb + (size_t)(k0 + n) * ND + d0 + dg * 16);
                float4 a = ep[0], b = ep[1], c = ep[2], d = ep[3];
                int db = dg * 16;
                es[(db + 0) * TN + n] = a.x;  es[(db + 1) * TN + n] = a.y;
                es[(db + 2) * TN + n] = a.z;  es[(db + 3) * TN + n] = a.w;
                es[(db + 4) * TN + n] = b.x;  es[(db + 5) * TN + n] = b.y;
                es[(db + 6) * TN + n] = b.z;  es[(db + 7) * TN + n] = b.w;
                es[(db + 8) * TN + n] = c.x;  es[(db + 9) * TN + n] = c.y;
                es[(db +10) * TN + n] = c.z;  es[(db +11) * TN + n] = c.w;
                es[(db +12) * TN + n] = d.x;  es[(db +13) * TN + n] = d.y;
                es[(db +14) * TN + n] = d.z;  es[(db +15) * TN + n] = d.w;
            }
            __syncthreads();
            #pragma unroll
            for (int dd = 0; dd < DC; dd++) {
                const float* zrow = &zs[(d0 + dd) * TM + ty * 8];
                ulonglong2 za = *(const ulonglong2*)(zrow);      // rows 0,1 | 2,3
                ulonglong2 zb = *(const ulonglong2*)(zrow + 4);  // rows 4,5 | 6,7
                float4 ae = *(const float4*)&es[dd * TN + tx * 4];
                unsigned long long e0 = dup2(ae.x);
                unsigned long long e1 = dup2(ae.y);
                unsigned long long e2 = dup2(ae.z);
                unsigned long long e3 = dup2(ae.w);
                fma2(acc[0][0], za.x, e0); fma2(acc[0][1], za.y, e0);
                fma2(acc[0][2], zb.x, e0); fma2(acc[0][3], zb.y, e0);
                fma2(acc[1][0], za.x, e1); fma2(acc[1][1], za.y, e1);
                fma2(acc[1][2], zb.x, e1); fma2(acc[1][3], zb.y, e1);
                fma2(acc[2][0], za.x, e2); fma2(acc[2][1], za.y, e2);
                fma2(acc[2][2], zb.x, e2); fma2(acc[2][3], zb.y, e2);
                fma2(acc[3][0], za.x, e3); fma2(acc[3][1], za.y, e3);
                fma2(acc[3][2], zb.x, e3); fma2(acc[3][3], zb.y, e3);
            }
        }
        // epilogue: distances + local argmin
        #pragma unroll
        for (int j = 0; j < 4; j++) {
            int k = k0 + tx * 4 + j;
            float en = __ldg(&g_enorm[k]);
            #pragma unroll
            for (int rp = 0; rp < 4; rp++) {
                unsigned long long a = acc[j][rp];
                float flo = __uint_as_float((unsigned int)a);
                float fhi = __uint_as_float((unsigned int)(a >> 32));
                float dlo = en - 2.f * flo;
                float dhi = en - 2.f * fhi;
                int ilo = rp * 2, ihi = rp * 2 + 1;
                if (dlo < bestv[ilo]) { bestv[ilo] = dlo; besti[ilo] = k; }
                if (dhi < bestv[ihi]) { bestv[ihi] = dhi; besti[ihi] = k; }
            }
        }
    }

    // Warp-level argmin reduction: each output row lives entirely in one warp.
    #pragma unroll
    for (int i = 0; i < 8; i++) {
        float bv = bestv[i]; int bi = besti[i];
        #pragma unroll
        for (int o = 16; o > 0; o >>= 1) {
            float ov = __shfl_xor_sync(0xffffffffu, bv, o);
            int   oi = __shfl_xor_sync(0xffffffffu, bi, o);
            if (ov < bv || (ov == bv && oi < bi)) { bv = ov; bi = oi; }
        }
        if (tx == 0) g_idx[b0 + ty * 8 + i] = bi;
    }
}

// ---------------------------------------------------------------------------
// Per-row: gather z_q -> out, loss accum, cluster_size++, segment-sum of z.
// One warp per row, 8 rows per block.
__global__ void k_scatter(const float* __restrict__ z,
                          const float* __restrict__ emb,
                          float* __restrict__ out) {
    __shared__ float ls[8];
    int warp = threadIdx.x >> 5, lane = threadIdx.x & 31;
    int b = blockIdx.x * 8 + warp;
    int idx = g_idx[b];
    const float4* zp = (const float4*)(z + (size_t)b * ND);
    const float4* ep = (const float4*)(emb + (size_t)idx * ND);
    float4* oq = (float4*)(out + O_ZQ + (size_t)b * ND);
    float* esum = g_esum + (size_t)idx * ND;
    float lsum = 0.f;
    #pragma unroll
    for (int j = lane; j < ND / 4; j += 32) {
        float4 zv = zp[j], ev = ep[j];
        oq[j] = ev;
        float dx = ev.x - zv.x, dy = ev.y - zv.y, dz = ev.z - zv.z, dw = ev.w - zv.w;
        lsum += dx * dx + dy * dy + dz * dz + dw * dw;
        atomicAdd(&esum[j * 4 + 0], zv.x);
        atomicAdd(&esum[j * 4 + 1], zv.y);
        atomicAdd(&esum[j * 4 + 2], zv.z);
        atomicAdd(&esum[j * 4 + 3], zv.w);
    }
    #pragma unroll
    for (int o = 16; o > 0; o >>= 1) lsum += __shfl_xor_sync(0xffffffffu, lsum, o);
    if (lane == 0) {
        ls[warp] = lsum;
        atomicAdd(&g_cs[idx], 1.f);
        out[O_IDX + b] = (float)idx;
    }
    __syncthreads();
    if (threadIdx.x == 0) {
        float s = 0.f;
        #pragma unroll
        for (int w = 0; w < 8; w++) s += ls[w];
        atomicAdd(&g_loss, s);
    }
}

// ---------------------------------------------------------------------------
// new_ema_cs (pre-dead), n = sum, perplexity accumulation.
__global__ void k_ema(const float* __restrict__ ema_cs) {
    __shared__ float sn[8], sp[8];
    int k = blockIdx.x * 256 + threadIdx.x;
    float cs = g_cs[k];
    float ncs = DECAY * ema_cs[k] + (1.f - DECAY) * cs;
    g_newcs[k] = ncs;
    float p = cs * (1.f / NB);
    float t = p * logf(p + 1e-10f);
    #pragma unroll
    for (int o = 16; o > 0; o >>= 1) {
        ncs += __shfl_xor_sync(0xffffffffu, ncs, o);
        t   += __shfl_xor_sync(0xffffffffu, t, o);
    }
    int warp = threadIdx.x >> 5, lane = threadIdx.x & 31;
    if (lane == 0) { sn[warp] = ncs; sp[warp] = t; }
    __syncthreads();
    if (threadIdx.x == 0) {
        float a = 0.f, b = 0.f;
        #pragma unroll
        for (int w = 0; w < 8; w++) { a += sn[w]; b += sp[w]; }
        atomicAdd(&g_n, a);
        atomicAdd(&g_plx, b);
    }
}

// ---------------------------------------------------------------------------
// Finalize codebook rows: smoothing, new_embedding, dead-code reinit; write out.
// NOTE: out+O_EMB and out+O_ES are only 8-byte aligned -> float2 stores.
__global__ void k_final(const float* __restrict__ z,
                        const float* __restrict__ ema_es,
                        const float* __restrict__ noise,
                        const int* __restrict__ reinit_idx,
                        float* __restrict__ out) {
    int k = blockIdx.x * 4 + (threadIdx.x >> 6);
    int dq = threadIdx.x & 63;   // float4 chunk index within the row
    float n = g_n;
    float ncs = g_newcs[k];
    float cs_sm = (ncs + EPSV) / (n + NK * EPSV) * n;
    bool dead = (ncs / n) < (1.f / NK / 10.f);
    int ridx = reinit_idx[k];

    float4 eo = ((const float4*)(ema_es + (size_t)k * ND))[dq];
    float4 s  = ((const float4*)(g_esum + (size_t)k * ND))[dq];
    float4 nes;
    nes.x = DECAY * eo.x + (1.f - DECAY) * s.x;
    nes.y = DECAY * eo.y + (1.f - DECAY) * s.y;
    nes.z = DECAY * eo.z + (1.f - DECAY) * s.z;
    nes.w = DECAY * eo.w + (1.f - DECAY) * s.w;
    float inv = 1.f / cs_sm;
    float4 nemb = make_float4(nes.x * inv, nes.y * inv, nes.z * inv, nes.w * inv);
    if (dead) {
        float4 zr = ((const float4*)(z + (size_t)ridx * ND))[dq];
        float4 nz = ((const float4*)(noise + (size_t)k * ND))[dq];
        float4 ri = make_float4(zr.x + nz.x, zr.y + nz.y, zr.z + nz.z, zr.w + nz.w);
        nemb = ri;
        nes = ri;
    }
    float2* oemb = (float2*)(out + O_EMB + (size_t)k * ND) + dq * 2;
    float2* oes  = (float2*)(out + O_ES  + (size_t)k * ND) + dq * 2;
    oemb[0] = make_float2(nemb.x, nemb.y);
    oemb[1] = make_float2(nemb.z, nemb.w);
    oes[0]  = make_float2(nes.x, nes.y);
    oes[1]  = make_float2(nes.z, nes.w);
    if (dq == 0) out[O_CS + k] = dead ? 1.f : ncs;
}

// ---------------------------------------------------------------------------
__global__ void k_scalars(float* __restrict__ out) {
    out[O_LOSS] = CCOST * g_loss / ((float)NB * (float)ND);
    out[O_PLX]  = expf(-g_plx);
}

// ---------------------------------------------------------------------------
extern "C" void kernel_launch(void* const* d_in, const int* in_sizes, int n_in,
                              void* d_out, int out_size) {
    const float* z        = (const float*)d_in[0];
    const float* emb      = (const float*)d_in[1];
    const float* ema_cs   = (const float*)d_in[2];
    const float* ema_es   = (const float*)d_in[3];
    const float* noise    = (const float*)d_in[4];
    const int*   ridx     = (const int*)d_in[5];
    float* out = (float*)d_out;

    constexpr size_t SMEM_ARGMIN = (size_t)(ND * TM + DC * TN) * 4;  // 80 KB
    static bool attr_set = false;
    if (!attr_set) {
        cudaFuncSetAttribute(k_argmin, cudaFuncAttributeMaxDynamicSharedMemorySize,
                             (int)SMEM_ARGMIN);
        attr_set = true;
    }

    k_zero<<<1024, 256>>>();
    k_enorm<<<NK / 8, 256>>>(emb);
    k_argmin<<<NB / TM, 256, SMEM_ARGMIN>>>(z, emb);
    k_scatter<<<NB / 8, 256>>>(z, emb, out);
    k_ema<<<NK / 256, 256>>>(ema_cs);
    k_final<<<NK / 4, 256>>>(z, ema_es, noise, ridx, out);
    k_scalars<<<1, 1>>>(out);
}

// round 8
// speedup vs baseline: 1.6619x; 1.3119x over previous
#include <cuda_runtime.h>
#include <cuda_bf16.h>
#include <math.h>
#include <float.h>
#include <stdint.h>

// Problem sizes
constexpr int NB = 32768;
constexpr int ND = 256;
constexpr int NK = 8192;
constexpr float DECAY = 0.99f;
constexpr float EPSV  = 1e-5f;
constexpr float CCOST = 0.25f;
constexpr float TAU   = 0.02f;   // argmin gap threshold for fp32 fixup

// Output layout (flattened reference tuple, float32)
constexpr size_t O_ZQ   = 0;
constexpr size_t O_LOSS = (size_t)NB * ND;            // 8388608
constexpr size_t O_IDX  = O_LOSS + 1;
constexpr size_t O_PLX  = O_IDX + NB;
constexpr size_t O_EMB  = O_PLX + 1;                  // 8B aligned only!
constexpr size_t O_CS   = O_EMB + (size_t)NK * ND;
constexpr size_t O_ES   = O_CS + NK;                  // 8B aligned only!

// Scratch (device globals — no allocation)
__device__ float g_enorm[NK];
__device__ int   g_idx[NB];
__device__ int   g_fix[NB];
__device__ float g_cs[NK];
__device__ float g_esum[(size_t)NK * ND];
__device__ float g_newcs[NK];
__device__ float g_loss;
__device__ float g_n;
__device__ float g_plx;
__device__ __nv_bfloat16 g_ehi[(size_t)NK * ND];
__device__ __nv_bfloat16 g_elo[(size_t)NK * ND];

// ============================ PTX helpers ==================================
__device__ __forceinline__ uint32_t smem_to_u32(const void* p) {
    uint32_t a;
    asm("{ .reg .u64 t; cvta.to.shared.u64 t, %1; cvt.u32.u64 %0, t; }"
        : "=r"(a) : "l"(p));
    return a;
}
__device__ __forceinline__ void cp_async16(uint32_t dst, const void* src) {
    asm volatile("cp.async.cg.shared.global [%0], [%1], 16;"
        :: "r"(dst), "l"(src) : "memory");
}
#define CP_COMMIT() asm volatile("cp.async.commit_group;" ::: "memory")
#define CP_WAIT_1() asm volatile("cp.async.wait_group 1;" ::: "memory")
#define CP_WAIT_0() asm volatile("cp.async.wait_group 0;" ::: "memory")

#define MMA_BF16(c, a, b) \
    asm volatile("mma.sync.aligned.m16n8k16.row.col.f32.bf16.bf16.f32 " \
        "{%0,%1,%2,%3}, {%4,%5,%6,%7}, {%8,%9}, {%0,%1,%2,%3};" \
        : "+f"((c)[0]), "+f"((c)[1]), "+f"((c)[2]), "+f"((c)[3]) \
        : "r"((a)[0]), "r"((a)[1]), "r"((a)[2]), "r"((a)[3]), \
          "r"((b)[0]), "r"((b)[1]))

// smem byte layout (k_argmin_mma)
constexpr int A_OFF  = 0;          // A_s[2][128][264] bf16 (hi, lo; +8 pad)
constexpr int A_ARR  = 67584;      // 128*264*2
constexpr int A_ROW  = 528;        // 264*2
constexpr int B_OFF  = 135168;     // B_s[2][128][72] bf16 (+8 pad)
constexpr int B_BUF  = 18432;      // 128*72*2
constexpr int B_ROW  = 144;        // 72*2
constexpr int EN_OFF = 172032;     // float[128]
constexpr int RV_OFF = 172544;     // float[128][4]
constexpr int RI_OFF = 174592;     // int[128][4]
constexpr int R2_OFF = 176640;     // float[128][4]
constexpr int SMEM_MMA = 178688;

// ======================= small kernels =====================================
__global__ void k_zero() {
    int i = blockIdx.x * blockDim.x + threadIdx.x;
    int stride = gridDim.x * blockDim.x;
    for (size_t j = i; j < (size_t)NK * ND; j += stride) g_esum[j] = 0.f;
    for (int j = i; j < NK; j += stride) g_cs[j] = 0.f;
    if (i == 0) { g_loss = 0.f; g_n = 0.f; g_plx = 0.f; }
}

// split embedding into bf16 hi + lo
__global__ void k_split(const float* __restrict__ emb) {
    size_t i = (size_t)(blockIdx.x * 256 + threadIdx.x) * 4;
    float4 v = *(const float4*)(emb + i);
    __nv_bfloat16 h0 = __float2bfloat16(v.x), h1 = __float2bfloat16(v.y);
    __nv_bfloat16 h2 = __float2bfloat16(v.z), h3 = __float2bfloat16(v.w);
    __nv_bfloat16 l0 = __float2bfloat16(v.x - __bfloat162float(h0));
    __nv_bfloat16 l1 = __float2bfloat16(v.y - __bfloat162float(h1));
    __nv_bfloat16 l2 = __float2bfloat16(v.z - __bfloat162float(h2));
    __nv_bfloat16 l3 = __float2bfloat16(v.w - __bfloat162float(h3));
    uint2 hp, lp;
    hp.x = (uint32_t)__bfloat16_as_ushort(h0) | ((uint32_t)__bfloat16_as_ushort(h1) << 16);
    hp.y = (uint32_t)__bfloat16_as_ushort(h2) | ((uint32_t)__bfloat16_as_ushort(h3) << 16);
    lp.x = (uint32_t)__bfloat16_as_ushort(l0) | ((uint32_t)__bfloat16_as_ushort(l1) << 16);
    lp.y = (uint32_t)__bfloat16_as_ushort(l2) | ((uint32_t)__bfloat16_as_ushort(l3) << 16);
    *(uint2*)(g_ehi + i) = hp;
    *(uint2*)(g_elo + i) = lp;
}

__global__ void k_enorm(const float* __restrict__ emb) {
    int warp = threadIdx.x >> 5, lane = threadIdx.x & 31;
    int k = blockIdx.x * 8 + warp;
    const float4* ep = (const float4*)(emb + (size_t)k * ND) + lane * 2;
    float4 a = ep[0], b = ep[1];
    float s = a.x*a.x + a.y*a.y + a.z*a.z + a.w*a.w
            + b.x*b.x + b.y*b.y + b.z*b.z + b.w*b.w;
    #pragma unroll
    for (int o = 16; o > 0; o >>= 1) s += __shfl_xor_sync(0xffffffffu, s, o);
    if (lane == 0) g_enorm[k] = s;
}

// ===================== mma.sync fused distance+argmin ======================
// Per CTA: 128 z rows x all 8192 codes. A = z split (hi|lo) resident in smem.
// 64 col-tiles of 128 codes; per tile 12 k64-chunks (3 terms x 4 kb).
// term0: zhi.ehi  term1: zhi.elo  term2: zlo.ehi  (fp32 accum)
// dist = enorm[k] - 2*dot ; per-lane best1/best2, fixup flag if gap < TAU.
__global__ __launch_bounds__(256, 1)
void k_argmin_mma(const float* __restrict__ z) {
    extern __shared__ char sm[];
    const uint32_t sbase = smem_to_u32(sm);
    const int tid = threadIdx.x;
    const int lane = tid & 31, warp = tid >> 5;
    const int wm = warp & 1, wn = warp >> 1;     // warp_m 0..1, warp_n 0..3
    const int gid = lane >> 2, tig = lane & 3;   // groupID, thread-in-group
    const int m0 = blockIdx.x * 128;

    auto issue_chunk = [&](int cc) {
        int tile = cc / 12, c = cc % 12;
        int t = c >> 2, kb = c & 3, buf = cc & 1;
        const __nv_bfloat16* src = (t == 1) ? g_elo : g_ehi;
        src += (size_t)(tile * 128) * ND + kb * 64;
        uint32_t dbase = sbase + B_OFF + buf * B_BUF;
        #pragma unroll
        for (int i = 0; i < 4; i++) {
            int th = tid + i * 256;
            int row = th >> 3, k8 = th & 7;
            cp_async16(dbase + row * B_ROW + k8 * 16,
                       src + (size_t)row * ND + k8 * 8);
        }
        CP_COMMIT();
    };

    issue_chunk(0);

    // Load A resident: split z rows into hi/lo bf16 in smem
    #pragma unroll 4
    for (int j = 0; j < 32; j++) {
        int gi = tid + j * 256;
        int row = gi >> 6, q = gi & 63;   // q = float4 index in row
        float4 v = ((const float4*)(z + (size_t)(m0 + row) * ND))[q];
        __nv_bfloat16 h0 = __float2bfloat16(v.x), h1 = __float2bfloat16(v.y);
        __nv_bfloat16 h2 = __float2bfloat16(v.z), h3 = __float2bfloat16(v.w);
        __nv_bfloat16 l0 = __float2bfloat16(v.x - __bfloat162float(h0));
        __nv_bfloat16 l1 = __float2bfloat16(v.y - __bfloat162float(h1));
        __nv_bfloat16 l2 = __float2bfloat16(v.z - __bfloat162float(h2));
        __nv_bfloat16 l3 = __float2bfloat16(v.w - __bfloat162float(h3));
        uint2 hp, lp;
        hp.x = (uint32_t)__bfloat16_as_ushort(h0) | ((uint32_t)__bfloat16_as_ushort(h1) << 16);
        hp.y = (uint32_t)__bfloat16_as_ushort(h2) | ((uint32_t)__bfloat16_as_ushort(h3) << 16);
        lp.x = (uint32_t)__bfloat16_as_ushort(l0) | ((uint32_t)__bfloat16_as_ushort(l1) << 16);
        lp.y = (uint32_t)__bfloat16_as_ushort(l2) | ((uint32_t)__bfloat16_as_ushort(l3) << 16);
        *(uint2*)(sm + A_OFF + row * A_ROW + q * 8) = hp;
        *(uint2*)(sm + A_OFF + A_ARR + row * A_ROW + q * 8) = lp;
    }

    float bv[8], b2[8];
    int bi[8];
    #pragma unroll
    for (int i = 0; i < 8; i++) { bv[i] = FLT_MAX; b2[i] = FLT_MAX; bi[i] = 0x7fffffff; }

    float acc[4][4][4];

    for (int cc = 0; cc < 768; cc++) {
        int tile = cc / 12, c = cc % 12, buf = cc & 1;

        if (c == 0) {
            if (tid < 128)
                ((float*)(sm + EN_OFF))[tid] = g_enorm[tile * 128 + tid];
            #pragma unroll
            for (int mf = 0; mf < 4; mf++)
                #pragma unroll
                for (int nf = 0; nf < 4; nf++)
                    #pragma unroll
                    for (int r = 0; r < 4; r++) acc[mf][nf][r] = 0.f;
        }

        // barrier 1: everyone done reading B[buf^1] (chunk cc-1) before refill
        __syncthreads();
        if (cc + 1 < 768) { issue_chunk(cc + 1); CP_WAIT_1(); }
        else              { CP_WAIT_0(); }
        // barrier 2: B[buf] (chunk cc) complete and visible to all threads
        __syncthreads();

        // compute chunk
        {
            int t = c >> 2, kb = c & 3;
            const char* Ab = sm + A_OFF + ((t == 2) ? A_ARR : 0);
            const char* Bb = sm + B_OFF + buf * B_BUF;
            #pragma unroll
            for (int ks = 0; ks < 4; ks++) {
                uint32_t a[4][4], b[4][2];
                int kcol = kb * 64 + ks * 16 + tig * 2;
                #pragma unroll
                for (int mf = 0; mf < 4; mf++) {
                    const char* p = Ab + (wm * 64 + mf * 16 + gid) * A_ROW + kcol * 2;
                    a[mf][0] = *(const uint32_t*)p;
                    a[mf][1] = *(const uint32_t*)(p + 8 * A_ROW);
                    a[mf][2] = *(const uint32_t*)(p + 16);
                    a[mf][3] = *(const uint32_t*)(p + 8 * A_ROW + 16);
                }
                int bk = ks * 16 + tig * 2;
                #pragma unroll
                for (int nf = 0; nf < 4; nf++) {
                    // FIX: include warp column offset wn*32 in the B row index
                    const char* p = Bb + (wn * 32 + nf * 8 + gid) * B_ROW + bk * 2;
                    b[nf][0] = *(const uint32_t*)p;
                    b[nf][1] = *(const uint32_t*)(p + 16);
                }
                #pragma unroll
                for (int mf = 0; mf < 4; mf++)
                    #pragma unroll
                    for (int nf = 0; nf < 4; nf++)
                        MMA_BF16(acc[mf][nf], a[mf], b[nf]);
            }
        }

        if (c == 11) {
            // epilogue: dist = enorm - 2*dot, update best1/best2
            int n0 = tile * 128;
            const float* en = (const float*)(sm + EN_OFF);
            #pragma unroll
            for (int nf = 0; nf < 4; nf++) {
                int cl = wn * 32 + nf * 8 + tig * 2;
                float e0 = en[cl], e1 = en[cl + 1];
                int gc0 = n0 + cl, gc1 = gc0 + 1;
                #pragma unroll
                for (int mf = 0; mf < 4; mf++) {
                    int l0 = mf * 2, l1 = mf * 2 + 1;
                    float d;
                    d = e0 - 2.f * acc[mf][nf][0];
                    if (d < bv[l0]) { b2[l0] = bv[l0]; bv[l0] = d; bi[l0] = gc0; }
                    else if (d < b2[l0]) b2[l0] = d;
                    d = e1 - 2.f * acc[mf][nf][1];
                    if (d < bv[l0]) { b2[l0] = bv[l0]; bv[l0] = d; bi[l0] = gc1; }
                    else if (d < b2[l0]) b2[l0] = d;
                    d = e0 - 2.f * acc[mf][nf][2];
                    if (d < bv[l1]) { b2[l1] = bv[l1]; bv[l1] = d; bi[l1] = gc0; }
                    else if (d < b2[l1]) b2[l1] = d;
                    d = e1 - 2.f * acc[mf][nf][3];
                    if (d < bv[l1]) { b2[l1] = bv[l1]; bv[l1] = d; bi[l1] = gc1; }
                    else if (d < b2[l1]) b2[l1] = d;
                }
            }
        }
    }

    // merge across lanes sharing a row (lane%4 partners: xor 1, xor 2)
    #pragma unroll
    for (int l = 0; l < 8; l++) {
        #pragma unroll
        for (int o = 1; o <= 2; o <<= 1) {
            float ov = __shfl_xor_sync(0xffffffffu, bv[l], o);
            int   oi = __shfl_xor_sync(0xffffffffu, bi[l], o);
            float o2 = __shfl_xor_sync(0xffffffffu, b2[l], o);
            float n2;
            if (ov < bv[l] || (ov == bv[l] && oi < bi[l])) {
                n2 = fminf(bv[l], o2);
                bv[l] = ov; bi[l] = oi;
            } else {
                n2 = fminf(ov, b2[l]);
            }
            b2[l] = fminf(b2[l], n2);
        }
    }
    if (tig == 0) {
        float* rv = (float*)(sm + RV_OFF);
        int*   ri = (int*)(sm + RI_OFF);
        float* r2 = (float*)(sm + R2_OFF);
        #pragma unroll
        for (int l = 0; l < 8; l++) {
            int mf = l >> 1, r = l & 1;
            int row = wm * 64 + mf * 16 + gid + r * 8;
            rv[row * 4 + wn] = bv[l];
            ri[row * 4 + wn] = bi[l];
            r2[row * 4 + wn] = b2[l];
        }
    }
    __syncthreads();
    if (tid < 128) {
        const float* rv = (const float*)(sm + RV_OFF);
        const int*   ri = (const int*)(sm + RI_OFF);
        const float* r2 = (const float*)(sm + R2_OFF);
        float v1 = rv[tid * 4], s2 = r2[tid * 4];
        int i1 = ri[tid * 4];
        #pragma unroll
        for (int w = 1; w < 4; w++) {
            float ov = rv[tid * 4 + w], o2 = r2[tid * 4 + w];
            int oi = ri[tid * 4 + w];
            float n2;
            if (ov < v1 || (ov == v1 && oi < i1)) {
                n2 = fminf(v1, o2); v1 = ov; i1 = oi;
            } else {
                n2 = fminf(ov, s2);
            }
            s2 = fminf(s2, n2);
        }
        g_idx[m0 + tid] = i1;
        g_fix[m0 + tid] = (s2 - v1 < TAU) ? 1 : 0;
    }
}

// fp32 exact re-argmin for rows with tiny gap
__global__ __launch_bounds__(256)
void k_fixup(const float* __restrict__ z, const float* __restrict__ emb) {
    int b = blockIdx.x;
    if (!g_fix[b]) return;
    __shared__ float zr[ND];
    __shared__ float sv[256];
    __shared__ int   si[256];
    zr[threadIdx.x] = z[(size_t)b * ND + threadIdx.x];
    __syncthreads();
    float bv = FLT_MAX; int bi = 0x7fffffff;
    for (int k = threadIdx.x; k < NK; k += 256) {
        const float4* ep = (const float4*)(emb + (size_t)k * ND);
        float dot = 0.f;
        #pragma unroll 16
        for (int q = 0; q < 64; ++q) {
            float4 e = ep[q];
            dot += zr[q*4+0]*e.x + zr[q*4+1]*e.y + zr[q*4+2]*e.z + zr[q*4+3]*e.w;
        }
        float dist = g_enorm[k] - 2.f * dot;
        if (dist < bv) { bv = dist; bi = k; }
    }
    sv[threadIdx.x] = bv; si[threadIdx.x] = bi;
    __syncthreads();
    for (int s = 128; s > 0; s >>= 1) {
        if (threadIdx.x < s) {
            float ov = sv[threadIdx.x + s]; int oi = si[threadIdx.x + s];
            if (ov < sv[threadIdx.x] || (ov == sv[threadIdx.x] && oi < si[threadIdx.x])) {
                sv[threadIdx.x] = ov; si[threadIdx.x] = oi;
            }
        }
        __syncthreads();
    }
    if (threadIdx.x == 0) g_idx[b] = si[0];
}

// ========================= post-argmin kernels =============================
__global__ void k_scatter(const float* __restrict__ z,
                          const float* __restrict__ emb,
                          float* __restrict__ out) {
    __shared__ float ls[8];
    int warp = threadIdx.x >> 5, lane = threadIdx.x & 31;
    int b = blockIdx.x * 8 + warp;
    int idx = g_idx[b];
    const float4* zp = (const float4*)(z + (size_t)b * ND);
    const float4* ep = (const float4*)(emb + (size_t)idx * ND);
    float4* oq = (float4*)(out + O_ZQ + (size_t)b * ND);
    float* esum = g_esum + (size_t)idx * ND;
    float lsum = 0.f;
    #pragma unroll
    for (int j = lane; j < ND / 4; j += 32) {
        float4 zv = zp[j], ev = ep[j];
        oq[j] = ev;
        float dx = ev.x - zv.x, dy = ev.y - zv.y, dz = ev.z - zv.z, dw = ev.w - zv.w;
        lsum += dx * dx + dy * dy + dz * dz + dw * dw;
        atomicAdd(&esum[j * 4 + 0], zv.x);
        atomicAdd(&esum[j * 4 + 1], zv.y);
        atomicAdd(&esum[j * 4 + 2], zv.z);
        atomicAdd(&esum[j * 4 + 3], zv.w);
    }
    #pragma unroll
    for (int o = 16; o > 0; o >>= 1) lsum += __shfl_xor_sync(0xffffffffu, lsum, o);
    if (lane == 0) {
        ls[warp] = lsum;
        atomicAdd(&g_cs[idx], 1.f);
        out[O_IDX + b] = (float)idx;
    }
    __syncthreads();
    if (threadIdx.x == 0) {
        float s = 0.f;
        #pragma unroll
        for (int w = 0; w < 8; w++) s += ls[w];
        atomicAdd(&g_loss, s);
    }
}

__global__ void k_ema(const float* __restrict__ ema_cs) {
    __shared__ float sn[8], sp[8];
    int k = blockIdx.x * 256 + threadIdx.x;
    float cs = g_cs[k];
    float ncs = DECAY * ema_cs[k] + (1.f - DECAY) * cs;
    g_newcs[k] = ncs;
    float p = cs * (1.f / NB);
    float t = p * logf(p + 1e-10f);
    #pragma unroll
    for (int o = 16; o > 0; o >>= 1) {
        ncs += __shfl_xor_sync(0xffffffffu, ncs, o);
        t   += __shfl_xor_sync(0xffffffffu, t, o);
    }
    int warp = threadIdx.x >> 5, lane = threadIdx.x & 31;
    if (lane == 0) { sn[warp] = ncs; sp[warp] = t; }
    __syncthreads();
    if (threadIdx.x == 0) {
        float a = 0.f, b = 0.f;
        #pragma unroll
        for (int w = 0; w < 8; w++) { a += sn[w]; b += sp[w]; }
        atomicAdd(&g_n, a);
        atomicAdd(&g_plx, b);
    }
}

__global__ void k_final(const float* __restrict__ z,
                        const float* __restrict__ ema_es,
                        const float* __restrict__ noise,
                        const int* __restrict__ reinit_idx,
                        float* __restrict__ out) {
    int k = blockIdx.x * 4 + (threadIdx.x >> 6);
    int dq = threadIdx.x & 63;
    float n = g_n;
    float ncs = g_newcs[k];
    float cs_sm = (ncs + EPSV) / (n + NK * EPSV) * n;
    bool dead = (ncs / n) < (1.f / NK / 10.f);
    int ridx = reinit_idx[k];

    float4 eo = ((const float4*)(ema_es + (size_t)k * ND))[dq];
    float4 s  = ((const float4*)(g_esum + (size_t)k * ND))[dq];
    float4 nes;
    nes.x = DECAY * eo.x + (1.f - DECAY) * s.x;
    nes.y = DECAY * eo.y + (1.f - DECAY) * s.y;
    nes.z = DECAY * eo.z + (1.f - DECAY) * s.z;
    nes.w = DECAY * eo.w + (1.f - DECAY) * s.w;
    float inv = 1.f / cs_sm;
    float4 nemb = make_float4(nes.x * inv, nes.y * inv, nes.z * inv, nes.w * inv);
    if (dead) {
        float4 zr = ((const float4*)(z + (size_t)ridx * ND))[dq];
        float4 nz = ((const float4*)(noise + (size_t)k * ND))[dq];
        float4 ri = make_float4(zr.x + nz.x, zr.y + nz.y, zr.z + nz.z, zr.w + nz.w);
        nemb = ri; nes = ri;
    }
    float2* oemb = (float2*)(out + O_EMB + (size_t)k * ND) + dq * 2;
    float2* oes  = (float2*)(out + O_ES  + (size_t)k * ND) + dq * 2;
    oemb[0] = make_float2(nemb.x, nemb.y);
    oemb[1] = make_float2(nemb.z, nemb.w);
    oes[0]  = make_float2(nes.x, nes.y);
    oes[1]  = make_float2(nes.z, nes.w);
    if (dq == 0) out[O_CS + k] = dead ? 1.f : ncs;
}

__global__ void k_scalars(float* __restrict__ out) {
    out[O_LOSS] = CCOST * g_loss / ((float)NB * (float)ND);
    out[O_PLX]  = expf(-g_plx);
}

// ---------------------------------------------------------------------------
extern "C" void kernel_launch(void* const* d_in, const int* in_sizes, int n_in,
                              void* d_out, int out_size) {
    const float* z      = (const float*)d_in[0];
    const float* emb    = (const float*)d_in[1];
    const float* ema_cs = (const float*)d_in[2];
    const float* ema_es = (const float*)d_in[3];
    const float* noise  = (const float*)d_in[4];
    const int*   ridx   = (const int*)d_in[5];
    float* out = (float*)d_out;

    static bool attr_set = false;
    if (!attr_set) {
        cudaFuncSetAttribute(k_argmin_mma,
                             cudaFuncAttributeMaxDynamicSharedMemorySize, SMEM_MMA);
        attr_set = true;
    }

    k_zero<<<1024, 256>>>();
    k_split<<<(NK * ND) / (256 * 4), 256>>>(emb);
    k_enorm<<<NK / 8, 256>>>(emb);
    k_argmin_mma<<<NB / 128, 256, SMEM_MMA>>>(z);
    k_fixup<<<NB, 256>>>(z, emb);
    k_scatter<<<NB / 8, 256>>>(z, emb, out);
    k_ema<<<NK / 256, 256>>>(ema_cs);
    k_final<<<NK / 4, 256>>>(z, ema_es, noise, ridx, out);
    k_scalars<<<1, 1>>>(out);
}

// round 10
// speedup vs baseline: 1.8133x; 1.0911x over previous
#include <cuda_runtime.h>
#include <cuda_bf16.h>
#include <math.h>
#include <float.h>
#include <stdint.h>

// Problem sizes
constexpr int NB = 32768;
constexpr int ND = 256;
constexpr int NK = 8192;
constexpr float DECAY = 0.99f;
constexpr float EPSV  = 1e-5f;
constexpr float CCOST = 0.25f;
constexpr float TAU   = 0.02f;   // argmin gap threshold for fp32 fixup

// Output layout (flattened reference tuple, float32)
constexpr size_t O_ZQ   = 0;
constexpr size_t O_LOSS = (size_t)NB * ND;            // 8388608
constexpr size_t O_IDX  = O_LOSS + 1;
constexpr size_t O_PLX  = O_IDX + NB;
constexpr size_t O_EMB  = O_PLX + 1;                  // 8B aligned only!
constexpr size_t O_CS   = O_EMB + (size_t)NK * ND;
constexpr size_t O_ES   = O_CS + NK;                  // 8B aligned only!

// Scratch (device globals — no allocation)
__device__ float g_enorm[NK];
__device__ int   g_idx[NB];
__device__ int   g_fix[NB];
__device__ float g_cs[NK];
__device__ float g_esum[(size_t)NK * ND];
__device__ float g_newcs[NK];
__device__ float g_loss;
__device__ float g_n;
__device__ float g_plx;
__device__ __nv_bfloat16 g_ehi[(size_t)NK * ND];
__device__ __nv_bfloat16 g_elo[(size_t)NK * ND];

// ============================ PTX helpers ==================================
__device__ __forceinline__ uint32_t smem_to_u32(const void* p) {
    uint32_t a;
    asm("{ .reg .u64 t; cvta.to.shared.u64 t, %1; cvt.u32.u64 %0, t; }"
        : "=r"(a) : "l"(p));
    return a;
}
__device__ __forceinline__ void cp_async16(uint32_t dst, const void* src) {
    asm volatile("cp.async.cg.shared.global [%0], [%1], 16;"
        :: "r"(dst), "l"(src) : "memory");
}
#define CP_COMMIT() asm volatile("cp.async.commit_group;" ::: "memory")
#define CP_WAIT_1() asm volatile("cp.async.wait_group 1;" ::: "memory")
#define CP_WAIT_0() asm volatile("cp.async.wait_group 0;" ::: "memory")

#define MMA_BF16(c, a, b) \
    asm volatile("mma.sync.aligned.m16n8k16.row.col.f32.bf16.bf16.f32 " \
        "{%0,%1,%2,%3}, {%4,%5,%6,%7}, {%8,%9}, {%0,%1,%2,%3};" \
        : "+f"((c)[0]), "+f"((c)[1]), "+f"((c)[2]), "+f"((c)[3]) \
        : "r"((a)[0]), "r"((a)[1]), "r"((a)[2]), "r"((a)[3]), \
          "r"((b)[0]), "r"((b)[1]))

#define LDSM_X4(r0, r1, r2, r3, addr) \
    asm volatile("ldmatrix.sync.aligned.m8n8.x4.shared.b16 {%0,%1,%2,%3}, [%4];" \
        : "=r"(r0), "=r"(r1), "=r"(r2), "=r"(r3) : "r"(addr))

// smem byte layout (k_argmin_mma)
constexpr int A_OFF  = 0;          // A_s[2][128][264] bf16 (hi, lo; +8 pad)
constexpr int A_ARR  = 67584;      // 128*264*2
constexpr int A_ROW  = 528;        // 264*2
constexpr int B_OFF  = 135168;     // B_s[2][128][72] bf16 (+8 pad)
constexpr int B_BUF  = 18432;      // 128*72*2
constexpr int B_ROW  = 144;        // 72*2
constexpr int EN_OFF = 172032;     // float[128]
constexpr int RV_OFF = 172544;     // float[128][4]
constexpr int RI_OFF = 174592;     // int[128][4]
constexpr int R2_OFF = 176640;     // float[128][4]
constexpr int SMEM_MMA = 178688;

// ======================= small kernels =====================================
__global__ void k_zero() {
    int i = blockIdx.x * blockDim.x + threadIdx.x;
    int stride = gridDim.x * blockDim.x;
    for (size_t j = i; j < (size_t)NK * ND; j += stride) g_esum[j] = 0.f;
    for (int j = i; j < NK; j += stride) g_cs[j] = 0.f;
    if (i == 0) { g_loss = 0.f; g_n = 0.f; g_plx = 0.f; }
}

// split embedding into bf16 hi + lo
__global__ void k_split(const float* __restrict__ emb) {
    size_t i = (size_t)(blockIdx.x * 256 + threadIdx.x) * 4;
    float4 v = *(const float4*)(emb + i);
    __nv_bfloat16 h0 = __float2bfloat16(v.x), h1 = __float2bfloat16(v.y);
    __nv_bfloat16 h2 = __float2bfloat16(v.z), h3 = __float2bfloat16(v.w);
    __nv_bfloat16 l0 = __float2bfloat16(v.x - __bfloat162float(h0));
    __nv_bfloat16 l1 = __float2bfloat16(v.y - __bfloat162float(h1));
    __nv_bfloat16 l2 = __float2bfloat16(v.z - __bfloat162float(h2));
    __nv_bfloat16 l3 = __float2bfloat16(v.w - __bfloat162float(h3));
    uint2 hp, lp;
    hp.x = (uint32_t)__bfloat16_as_ushort(h0) | ((uint32_t)__bfloat16_as_ushort(h1) << 16);
    hp.y = (uint32_t)__bfloat16_as_ushort(h2) | ((uint32_t)__bfloat16_as_ushort(h3) << 16);
    lp.x = (uint32_t)__bfloat16_as_ushort(l0) | ((uint32_t)__bfloat16_as_ushort(l1) << 16);
    lp.y = (uint32_t)__bfloat16_as_ushort(l2) | ((uint32_t)__bfloat16_as_ushort(l3) << 16);
    *(uint2*)(g_ehi + i) = hp;
    *(uint2*)(g_elo + i) = lp;
}

__global__ void k_enorm(const float* __restrict__ emb) {
    int warp = threadIdx.x >> 5, lane = threadIdx.x & 31;
    int k = blockIdx.x * 8 + warp;
    const float4* ep = (const float4*)(emb + (size_t)k * ND) + lane * 2;
    float4 a = ep[0], b = ep[1];
    float s = a.x*a.x + a.y*a.y + a.z*a.z + a.w*a.w
            + b.x*b.x + b.y*b.y + b.z*b.z + b.w*b.w;
    #pragma unroll
    for (int o = 16; o > 0; o >>= 1) s += __shfl_xor_sync(0xffffffffu, s, o);
    if (lane == 0) g_enorm[k] = s;
}

// ===================== mma.sync fused distance+argmin ======================
// Per CTA: 128 z rows x all 8192 codes. 512 threads = 16 warps, 4(M)x4(N).
// Warp tile 32x32. A = z split (hi|lo) resident in smem; B double-buffered.
// Fragments via NON-trans ldmatrix for both A and B:
//   A smem [row][k-contig] -> a0..a3 spec; B smem [n][k-contig] is col-major
//   for row.col mma, so b regs (2 consecutive k per n) come from non-trans too.
// dist = enorm[k] - 2*dot ; per-lane best1/best2, fixup flag if gap < TAU.
__global__ __launch_bounds__(512, 1)
void k_argmin_mma(const float* __restrict__ z) {
    extern __shared__ char sm[];
    const uint32_t sbase = smem_to_u32(sm);
    const int tid = threadIdx.x;
    const int lane = tid & 31, warp = tid >> 5;
    const int wm = warp & 3, wn = warp >> 2;     // warp_m 0..3, warp_n 0..3
    const int gid = lane >> 2, tig = lane & 3;   // groupID, thread-in-group
    const int m0 = blockIdx.x * 128;

    auto issue_chunk = [&](int cc) {
        int tile = cc / 12, c = cc % 12;
        int t = c >> 2, kb = c & 3, buf = cc & 1;
        const __nv_bfloat16* src = (t == 1) ? g_elo : g_ehi;
        src += (size_t)(tile * 128) * ND + kb * 64;
        uint32_t dbase = sbase + B_OFF + buf * B_BUF;
        #pragma unroll
        for (int i = 0; i < 2; i++) {
            int th = tid + i * 512;
            int row = th >> 3, k8 = th & 7;
            cp_async16(dbase + row * B_ROW + k8 * 16,
                       src + (size_t)row * ND + k8 * 8);
        }
        CP_COMMIT();
    };

    issue_chunk(0);

    // Load A resident: split z rows into hi/lo bf16 in smem
    #pragma unroll 4
    for (int j = 0; j < 16; j++) {
        int gi = tid + j * 512;
        int row = gi >> 6, q = gi & 63;   // q = float4 index in row
        float4 v = ((const float4*)(z + (size_t)(m0 + row) * ND))[q];
        __nv_bfloat16 h0 = __float2bfloat16(v.x), h1 = __float2bfloat16(v.y);
        __nv_bfloat16 h2 = __float2bfloat16(v.z), h3 = __float2bfloat16(v.w);
        __nv_bfloat16 l0 = __float2bfloat16(v.x - __bfloat162float(h0));
        __nv_bfloat16 l1 = __float2bfloat16(v.y - __bfloat162float(h1));
        __nv_bfloat16 l2 = __float2bfloat16(v.z - __bfloat162float(h2));
        __nv_bfloat16 l3 = __float2bfloat16(v.w - __bfloat162float(h3));
        uint2 hp, lp;
        hp.x = (uint32_t)__bfloat16_as_ushort(h0) | ((uint32_t)__bfloat16_as_ushort(h1) << 16);
        hp.y = (uint32_t)__bfloat16_as_ushort(h2) | ((uint32_t)__bfloat16_as_ushort(h3) << 16);
        lp.x = (uint32_t)__bfloat16_as_ushort(l0) | ((uint32_t)__bfloat16_as_ushort(l1) << 16);
        lp.y = (uint32_t)__bfloat16_as_ushort(l2) | ((uint32_t)__bfloat16_as_ushort(l3) << 16);
        *(uint2*)(sm + A_OFF + row * A_ROW + q * 8) = hp;
        *(uint2*)(sm + A_OFF + A_ARR + row * A_ROW + q * 8) = lp;
    }

    float bv[4], b2[4];
    int bi[4];
    #pragma unroll
    for (int i = 0; i < 4; i++) { bv[i] = FLT_MAX; b2[i] = FLT_MAX; bi[i] = 0x7fffffff; }

    float acc[2][4][4];

    // ldmatrix lane-address components (constant per thread)
    const int a_row_l = (lane & 15);           // A: row within m16
    const int a_kh    = (lane >> 4) * 16;      // A: byte offset for k-half
    const int b_row_l = (lane & 7) + ((lane >> 4) & 1) * 8;  // B: n row within n16
    const int b_kh    = ((lane >> 3) & 1) * 16;              // B: byte offset k-half

    for (int cc = 0; cc < 768; cc++) {
        int tile = cc / 12, c = cc % 12, buf = cc & 1;

        if (c == 0) {
            if (tid < 128)
                ((float*)(sm + EN_OFF))[tid] = g_enorm[tile * 128 + tid];
            #pragma unroll
            for (int mf = 0; mf < 2; mf++)
                #pragma unroll
                for (int nf = 0; nf < 4; nf++)
                    #pragma unroll
                    for (int r = 0; r < 4; r++) acc[mf][nf][r] = 0.f;
        }

        // barrier 1: everyone done reading B[buf^1] (chunk cc-1) before refill
        __syncthreads();
        if (cc + 1 < 768) { issue_chunk(cc + 1); CP_WAIT_1(); }
        else              { CP_WAIT_0(); }
        // barrier 2: B[buf] (chunk cc) complete and visible to all threads
        __syncthreads();

        // compute chunk
        {
            int t = c >> 2, kb = c & 3;
            uint32_t Ab = sbase + A_OFF + ((t == 2) ? A_ARR : 0);
            uint32_t Bb = sbase + B_OFF + buf * B_BUF;
            #pragma unroll
            for (int ks = 0; ks < 4; ks++) {
                uint32_t a[2][4], b[4][2];
                int kbyte = (kb * 64 + ks * 16) * 2;
                #pragma unroll
                for (int mf = 0; mf < 2; mf++) {
                    uint32_t addr = Ab + (wm * 32 + mf * 16 + a_row_l) * A_ROW
                                  + kbyte + a_kh;
                    LDSM_X4(a[mf][0], a[mf][1], a[mf][2], a[mf][3], addr);
                }
                int bkbyte = ks * 16 * 2;
                #pragma unroll
                for (int np = 0; np < 2; np++) {
                    uint32_t addr = Bb + (wn * 32 + np * 16 + b_row_l) * B_ROW
                                  + bkbyte + b_kh;
                    // non-trans: m0=(n0-7,k0-7) m1=(n0-7,k8-15) m2=(n8-15,k0-7) m3=(n8-15,k8-15)
                    LDSM_X4(b[np*2][0], b[np*2][1], b[np*2+1][0], b[np*2+1][1], addr);
                }
                #pragma unroll
                for (int mf = 0; mf < 2; mf++)
                    #pragma unroll
                    for (int nf = 0; nf < 4; nf++)
                        MMA_BF16(acc[mf][nf], a[mf], b[nf]);
            }
        }

        if (c == 11) {
            // epilogue: dist = enorm - 2*dot, update best1/best2
            int n0 = tile * 128;
            const float* en = (const float*)(sm + EN_OFF);
            #pragma unroll
            for (int nf = 0; nf < 4; nf++) {
                int cl = wn * 32 + nf * 8 + tig * 2;
                float e0 = en[cl], e1 = en[cl + 1];
                int gc0 = n0 + cl, gc1 = gc0 + 1;
                #pragma unroll
                for (int mf = 0; mf < 2; mf++) {
                    int l0 = mf * 2, l1 = mf * 2 + 1;
                    float d;
                    d = e0 - 2.f * acc[mf][nf][0];
                    if (d < bv[l0]) { b2[l0] = bv[l0]; bv[l0] = d; bi[l0] = gc0; }
                    else if (d < b2[l0]) b2[l0] = d;
                    d = e1 - 2.f * acc[mf][nf][1];
                    if (d < bv[l0]) { b2[l0] = bv[l0]; bv[l0] = d; bi[l0] = gc1; }
                    else if (d < b2[l0]) b2[l0] = d;
                    d = e0 - 2.f * acc[mf][nf][2];
                    if (d < bv[l1]) { b2[l1] = bv[l1]; bv[l1] = d; bi[l1] = gc0; }
                    else if (d < b2[l1]) b2[l1] = d;
                    d = e1 - 2.f * acc[mf][nf][3];
                    if (d < bv[l1]) { b2[l1] = bv[l1]; bv[l1] = d; bi[l1] = gc1; }
                    else if (d < b2[l1]) b2[l1] = d;
                }
            }
        }
    }

    // merge across lanes sharing a row (lane%4 partners: xor 1, xor 2)
    #pragma unroll
    for (int l = 0; l < 4; l++) {
        #pragma unroll
        for (int o = 1; o <= 2; o <<= 1) {
            float ov = __shfl_xor_sync(0xffffffffu, bv[l], o);
            int   oi = __shfl_xor_sync(0xffffffffu, bi[l], o);
            float o2 = __shfl_xor_sync(0xffffffffu, b2[l], o);
            float n2;
            if (ov < bv[l] || (ov == bv[l] && oi < bi[l])) {
                n2 = fminf(bv[l], o2);
                bv[l] = ov; bi[l] = oi;
            } else {
                n2 = fminf(ov, b2[l]);
            }
            b2[l] = fminf(b2[l], n2);
        }
    }
    if (tig == 0) {
        float* rv = (float*)(sm + RV_OFF);
        int*   ri = (int*)(sm + RI_OFF);
        float* r2 = (float*)(sm + R2_OFF);
        #pragma unroll
        for (int l = 0; l < 4; l++) {
            int mf = l >> 1, r = l & 1;
            int row = wm * 32 + mf * 16 + gid + r * 8;
            rv[row * 4 + wn] = bv[l];
            ri[row * 4 + wn] = bi[l];
            r2[row * 4 + wn] = b2[l];
        }
    }
    __syncthreads();
    if (tid < 128) {
        const float* rv = (const float*)(sm + RV_OFF);
        const int*   ri = (const int*)(sm + RI_OFF);
        const float* r2 = (const float*)(sm + R2_OFF);
        float v1 = rv[tid * 4], s2 = r2[tid * 4];
        int i1 = ri[tid * 4];
        #pragma unroll
        for (int w = 1; w < 4; w++) {
            float ov = rv[tid * 4 + w], o2 = r2[tid * 4 + w];
            int oi = ri[tid * 4 + w];
            float n2;
            if (ov < v1 || (ov == v1 && oi < i1)) {
                n2 = fminf(v1, o2); v1 = ov; i1 = oi;
            } else {
                n2 = fminf(ov, s2);
            }
            s2 = fminf(s2, n2);
        }
        g_idx[m0 + tid] = i1;
        g_fix[m0 + tid] = (s2 - v1 < TAU) ? 1 : 0;
    }
}

// fp32 exact re-argmin for rows with tiny gap
__global__ __launch_bounds__(256)
void k_fixup(const float* __restrict__ z, const float* __restrict__ emb) {
    int b = blockIdx.x;
    if (!g_fix[b]) return;
    __shared__ float zr[ND];
    __shared__ float sv[256];
    __shared__ int   si[256];
    zr[threadIdx.x] = z[(size_t)b * ND + threadIdx.x];
    __syncthreads();
    float bv = FLT_MAX; int bi = 0x7fffffff;
    for (int k = threadIdx.x; k < NK; k += 256) {
        const float4* ep = (const float4*)(emb + (size_t)k * ND);
        float dot = 0.f;
        #pragma unroll 16
        for (int q = 0; q < 64; ++q) {
            float4 e = ep[q];
            dot += zr[q*4+0]*e.x + zr[q*4+1]*e.y + zr[q*4+2]*e.z + zr[q*4+3]*e.w;
        }
        float dist = g_enorm[k] - 2.f * dot;
        if (dist < bv) { bv = dist; bi = k; }
    }
    sv[threadIdx.x] = bv; si[threadIdx.x] = bi;
    __syncthreads();
    for (int s = 128; s > 0; s >>= 1) {
        if (threadIdx.x < s) {
            float ov = sv[threadIdx.x + s]; int oi = si[threadIdx.x + s];
            if (ov < sv[threadIdx.x] || (ov == sv[threadIdx.x] && oi < si[threadIdx.x])) {
                sv[threadIdx.x] = ov; si[threadIdx.x] = oi;
            }
        }
        __syncthreads();
    }
    if (threadIdx.x == 0) g_idx[b] = si[0];
}

// ========================= post-argmin kernels =============================
__global__ void k_scatter(const float* __restrict__ z,
                          const float* __restrict__ emb,
                          float* __restrict__ out) {
    __shared__ float ls[8];
    int warp = threadIdx.x >> 5, lane = threadIdx.x & 31;
    int b = blockIdx.x * 8 + warp;
    int idx = g_idx[b];
    const float4* zp = (const float4*)(z + (size_t)b * ND);
    const float4* ep = (const float4*)(emb + (size_t)idx * ND);
    float4* oq = (float4*)(out + O_ZQ + (size_t)b * ND);
    float* esum = g_esum + (size_t)idx * ND;
    float lsum = 0.f;
    #pragma unroll
    for (int j = lane; j < ND / 4; j += 32) {
        float4 zv = zp[j], ev = ep[j];
        oq[j] = ev;
        float dx = ev.x - zv.x, dy = ev.y - zv.y, dz = ev.z - zv.z, dw = ev.w - zv.w;
        lsum += dx * dx + dy * dy + dz * dz + dw * dw;
        atomicAdd(&esum[j * 4 + 0], zv.x);
        atomicAdd(&esum[j * 4 + 1], zv.y);
        atomicAdd(&esum[j * 4 + 2], zv.z);
        atomicAdd(&esum[j * 4 + 3], zv.w);
    }
    #pragma unroll
    for (int o = 16; o > 0; o >>= 1) lsum += __shfl_xor_sync(0xffffffffu, lsum, o);
    if (lane == 0) {
        ls[warp] = lsum;
        atomicAdd(&g_cs[idx], 1.f);
        out[O_IDX + b] = (float)idx;
    }
    __syncthreads();
    if (threadIdx.x == 0) {
        float s = 0.f;
        #pragma unroll
        for (int w = 0; w < 8; w++) s += ls[w];
        atomicAdd(&g_loss, s);
    }
}

__global__ void k_ema(const float* __restrict__ ema_cs) {
    __shared__ float sn[8], sp[8];
    int k = blockIdx.x * 256 + threadIdx.x;
    float cs = g_cs[k];
    float ncs = DECAY * ema_cs[k] + (1.f - DECAY) * cs;
    g_newcs[k] = ncs;
    float p = cs * (1.f / NB);
    float t = p * logf(p + 1e-10f);
    #pragma unroll
    for (int o = 16; o > 0; o >>= 1) {
        ncs += __shfl_xor_sync(0xffffffffu, ncs, o);
        t   += __shfl_xor_sync(0xffffffffu, t, o);
    }
    int warp = threadIdx.x >> 5, lane = threadIdx.x & 31;
    if (lane == 0) { sn[warp] = ncs; sp[warp] = t; }
    __syncthreads();
    if (threadIdx.x == 0) {
        float a = 0.f, b = 0.f;
        #pragma unroll
        for (int w = 0; w < 8; w++) { a += sn[w]; b += sp[w]; }
        atomicAdd(&g_n, a);
        atomicAdd(&g_plx, b);
    }
}

__global__ void k_final(const float* __restrict__ z,
                        const float* __restrict__ ema_es,
                        const float* __restrict__ noise,
                        const int* __restrict__ reinit_idx,
                        float* __restrict__ out) {
    int k = blockIdx.x * 4 + (threadIdx.x >> 6);
    int dq = threadIdx.x & 63;
    float n = g_n;
    float ncs = g_newcs[k];
    float cs_sm = (ncs + EPSV) / (n + NK * EPSV) * n;
    bool dead = (ncs / n) < (1.f / NK / 10.f);
    int ridx = reinit_idx[k];

    float4 eo = ((const float4*)(ema_es + (size_t)k * ND))[dq];
    float4 s  = ((const float4*)(g_esum + (size_t)k * ND))[dq];
    float4 nes;
    nes.x = DECAY * eo.x + (1.f - DECAY) * s.x;
    nes.y = DECAY * eo.y + (1.f - DECAY) * s.y;
    nes.z = DECAY * eo.z + (1.f - DECAY) * s.z;
    nes.w = DECAY * eo.w + (1.f - DECAY) * s.w;
    float inv = 1.f / cs_sm;
    float4 nemb = make_float4(nes.x * inv, nes.y * inv, nes.z * inv, nes.w * inv);
    if (dead) {
        float4 zr = ((const float4*)(z + (size_t)ridx * ND))[dq];
        float4 nz = ((const float4*)(noise + (size_t)k * ND))[dq];
        float4 ri = make_float4(zr.x + nz.x, zr.y + nz.y, zr.z + nz.z, zr.w + nz.w);
        nemb = ri; nes = ri;
    }
    float2* oemb = (float2*)(out + O_EMB + (size_t)k * ND) + dq * 2;
    float2* oes  = (float2*)(out + O_ES  + (size_t)k * ND) + dq * 2;
    oemb[0] = make_float2(nemb.x, nemb.y);
    oemb[1] = make_float2(nemb.z, nemb.w);
    oes[0]  = make_float2(nes.x, nes.y);
    oes[1]  = make_float2(nes.z, nes.w);
    if (dq == 0) out[O_CS + k] = dead ? 1.f : ncs;
}

__global__ void k_scalars(float* __restrict__ out) {
    out[O_LOSS] = CCOST * g_loss / ((float)NB * (float)ND);
    out[O_PLX]  = expf(-g_plx);
}

// ---------------------------------------------------------------------------
extern "C" void kernel_launch(void* const* d_in, const int* in_sizes, int n_in,
                              void* d_out, int out_size) {
    const float* z      = (const float*)d_in[0];
    const float* emb    = (const float*)d_in[1];
    const float* ema_cs = (const float*)d_in[2];
    const float* ema_es = (const float*)d_in[3];
    const float* noise  = (const float*)d_in[4];
    const int*   ridx   = (const int*)d_in[5];
    float* out = (float*)d_out;

    static bool attr_set = false;
    if (!attr_set) {
        cudaFuncSetAttribute(k_argmin_mma,
                             cudaFuncAttributeMaxDynamicSharedMemorySize, SMEM_MMA);
        attr_set = true;
    }

    k_zero<<<1024, 256>>>();
    k_split<<<(NK * ND) / (256 * 4), 256>>>(emb);
    k_enorm<<<NK / 8, 256>>>(emb);
    k_argmin_mma<<<NB / 128, 512, SMEM_MMA>>>(z);
    k_fixup<<<NB, 256>>>(z, emb);
    k_scatter<<<NB / 8, 256>>>(z, emb, out);
    k_ema<<<NK / 256, 256>>>(ema_cs);
    k_final<<<NK / 4, 256>>>(z, ema_es, noise, ridx, out);
    k_scalars<<<1, 1>>>(out);
}

// round 13
// speedup vs baseline: 5.0506x; 2.7853x over previous
#include <cuda_runtime.h>
#include <cuda_fp16.h>
#include <math.h>
#include <float.h>
#include <stdint.h>

// Problem sizes
constexpr int NB = 32768;
constexpr int ND = 256;
constexpr int NK = 8192;
constexpr float DECAY = 0.99f;
constexpr float EPSV  = 1e-5f;
constexpr float CCOST = 0.25f;
constexpr float TAU   = 0.15f;   // argmin gap threshold for fp32 fixup

// Output layout (flattened reference tuple, float32)
constexpr size_t O_ZQ   = 0;
constexpr size_t O_LOSS = (size_t)NB * ND;            // 8388608
constexpr size_t O_IDX  = O_LOSS + 1;
constexpr size_t O_PLX  = O_IDX + NB;
constexpr size_t O_EMB  = O_PLX + 1;                  // 8B aligned only!
constexpr size_t O_CS   = O_EMB + (size_t)NK * ND;
constexpr size_t O_ES   = O_CS + NK;                  // 8B aligned only!

// Scratch (device globals — no allocation)
__device__ float g_enorm[NK];
__device__ int   g_idx[NB];
__device__ int   g_fix[NB];
__device__ int   g_fixlist[NB];
__device__ int   g_nfix;
__device__ unsigned long long g_best[NB];
__device__ float g_cs[NK];
__device__ float g_esum[(size_t)NK * ND];
__device__ float g_newcs[NK];
__device__ float g_loss;
__device__ float g_n;
__device__ float g_plx;
__device__ __half g_eh[(size_t)NK * ND];

// ============================ PTX helpers ==================================
__device__ __forceinline__ uint32_t smem_to_u32(const void* p) {
    uint32_t a;
    asm("{ .reg .u64 t; cvta.to.shared.u64 t, %1; cvt.u32.u64 %0, t; }"
        : "=r"(a) : "l"(p));
    return a;
}
__device__ __forceinline__ void cp_async16(uint32_t dst, const void* src) {
    asm volatile("cp.async.cg.shared.global [%0], [%1], 16;"
        :: "r"(dst), "l"(src) : "memory");
}
#define CP_COMMIT() asm volatile("cp.async.commit_group;" ::: "memory")
#define CP_WAIT_1() asm volatile("cp.async.wait_group 1;" ::: "memory")
#define CP_WAIT_0() asm volatile("cp.async.wait_group 0;" ::: "memory")

#define MMA_F16(c, a, b) \
    asm volatile("mma.sync.aligned.m16n8k16.row.col.f32.f16.f16.f32 " \
        "{%0,%1,%2,%3}, {%4,%5,%6,%7}, {%8,%9}, {%0,%1,%2,%3};" \
        : "+f"((c)[0]), "+f"((c)[1]), "+f"((c)[2]), "+f"((c)[3]) \
        : "r"((a)[0]), "r"((a)[1]), "r"((a)[2]), "r"((a)[3]), \
          "r"((b)[0]), "r"((b)[1]))

#define LDSM_X4(r0, r1, r2, r3, addr) \
    asm volatile("ldmatrix.sync.aligned.m8n8.x4.shared.b16 {%0,%1,%2,%3}, [%4];" \
        : "=r"(r0), "=r"(r1), "=r"(r2), "=r"(r3) : "r"(addr))

// sortable key for fp32 (any sign) + index tiebreak (lower idx wins)
__device__ __forceinline__ unsigned long long pack_key(float d, int k) {
    uint32_t b = __float_as_uint(d);
    b = (b & 0x80000000u) ? ~b : (b | 0x80000000u);
    return ((unsigned long long)b << 32) | (uint32_t)k;
}

// smem byte layout (k_argmin_mma): fp16 single-pass, full-K tiles
constexpr int A_OFF  = 0;          // A_s[128][264] fp16 (+8 pad)
constexpr int A_ROW  = 528;        // 264*2 bytes
constexpr int B_OFF  = 67584;      // A ends: 128*528
constexpr int B_BUF  = 67584;      // B_s[128][264] fp16 per buffer
constexpr int B_ROW  = 528;
constexpr int EN_OFF = B_OFF + 2 * B_BUF;   // 202752, float[128]
constexpr int RV_OFF = EN_OFF + 512;        // float[128][4]
constexpr int RI_OFF = RV_OFF + 2048;       // int[128][4]
constexpr int R2_OFF = RI_OFF + 2048;       // float[128][4]
constexpr int SMEM_MMA = R2_OFF + 2048;     // 209408

// ======================= small kernels =====================================
__global__ void k_zero() {
    int i = blockIdx.x * blockDim.x + threadIdx.x;
    int stride = gridDim.x * blockDim.x;
    for (size_t j = i; j < (size_t)NK * ND; j += stride) g_esum[j] = 0.f;
    for (int j = i; j < NK; j += stride) g_cs[j] = 0.f;
    for (int j = i; j < NB; j += stride) g_best[j] = ~0ull;
    if (i == 0) { g_loss = 0.f; g_n = 0.f; g_plx = 0.f; g_nfix = 0; }
}

// convert embedding to fp16
__global__ void k_split(const float* __restrict__ emb) {
    size_t i = (size_t)(blockIdx.x * 256 + threadIdx.x) * 4;
    float4 v = *(const float4*)(emb + i);
    __half2 h01 = __floats2half2_rn(v.x, v.y);
    __half2 h23 = __floats2half2_rn(v.z, v.w);
    uint2 hp;
    hp.x = *(uint32_t*)&h01;
    hp.y = *(uint32_t*)&h23;
    *(uint2*)(g_eh + i) = hp;
}

__global__ void k_enorm(const float* __restrict__ emb) {
    int warp = threadIdx.x >> 5, lane = threadIdx.x & 31;
    int k = blockIdx.x * 8 + warp;
    const float4* ep = (const float4*)(emb + (size_t)k * ND) + lane * 2;
    float4 a = ep[0], b = ep[1];
    float s = a.x*a.x + a.y*a.y + a.z*a.z + a.w*a.w
            + b.x*b.x + b.y*b.y + b.z*b.z + b.w*b.w;
    #pragma unroll
    for (int o = 16; o > 0; o >>= 1) s += __shfl_xor_sync(0xffffffffu, s, o);
    if (lane == 0) g_enorm[k] = s;
}

// ===================== fp16 mma.sync fused distance+argmin =================
// Per CTA: 128 z rows x all 8192 codes. 512 threads = 16 warps, 4(M)x4(N).
// Single fp16 pass (error ~0.02 on distances; rows with gap<TAU get fp32 fixup).
// A = z fp16 resident in smem; B = full-K 128-code tiles, double-buffered.
__global__ __launch_bounds__(512, 1)
void k_argmin_mma(const float* __restrict__ z) {
    extern __shared__ char sm[];
    const uint32_t sbase = smem_to_u32(sm);
    const int tid = threadIdx.x;
    const int lane = tid & 31, warp = tid >> 5;
    const int wm = warp & 3, wn = warp >> 2;     // warp_m 0..3, warp_n 0..3
    const int gid = lane >> 2, tig = lane & 3;
    const int m0 = blockIdx.x * 128;

    auto issue_tile = [&](int t) {
        const __half* src = g_eh + (size_t)(t * 128) * ND;
        uint32_t dbase = sbase + B_OFF + (t & 1) * B_BUF;
        #pragma unroll
        for (int i = 0; i < 8; i++) {
            int th = tid + i * 512;      // 4096 cp16 total (128 rows x 512B)
            int row = th >> 5, c16 = th & 31;
            cp_async16(dbase + row * B_ROW + c16 * 16,
                       src + (size_t)row * ND + c16 * 8);
        }
        CP_COMMIT();
    };

    issue_tile(0);

    // A resident: convert z rows to fp16 in smem
    #pragma unroll 4
    for (int j = 0; j < 16; j++) {
        int gi = tid + j * 512;          // 8192 float4 chunks
        int row = gi >> 6, q = gi & 63;
        float4 v = ((const float4*)(z + (size_t)(m0 + row) * ND))[q];
        __half2 h01 = __floats2half2_rn(v.x, v.y);
        __half2 h23 = __floats2half2_rn(v.z, v.w);
        uint2 hp;
        hp.x = *(uint32_t*)&h01;
        hp.y = *(uint32_t*)&h23;
        *(uint2*)(sm + A_OFF + row * A_ROW + q * 8) = hp;
    }

    float bv[4], b2[4];
    int bi[4];
    #pragma unroll
    for (int i = 0; i < 4; i++) { bv[i] = FLT_MAX; b2[i] = FLT_MAX; bi[i] = 0x7fffffff; }

    // ldmatrix lane-address components
    const int a_row_l = (lane & 15);
    const int a_kh    = (lane >> 4) * 16;
    const int b_row_l = (lane & 7) + ((lane >> 4) & 1) * 8;
    const int b_kh    = ((lane >> 3) & 1) * 16;

    for (int t = 0; t < 64; t++) {
        int buf = t & 1;
        // barrier 1: epilogue reads of tile t-1 done; B[buf^1] free for refill
        __syncthreads();
        if (tid < 128)
            ((float*)(sm + EN_OFF))[tid] = g_enorm[t * 128 + tid];
        if (t + 1 < 64) { issue_tile(t + 1); CP_WAIT_1(); }
        else            { CP_WAIT_0(); }
        // barrier 2: B[buf] complete + EN visible
        __syncthreads();

        float acc[2][4][4];
        #pragma unroll
        for (int mf = 0; mf < 2; mf++)
            #pragma unroll
            for (int nf = 0; nf < 4; nf++)
                #pragma unroll
                for (int r = 0; r < 4; r++) acc[mf][nf][r] = 0.f;

        uint32_t Ab = sbase + A_OFF;
        uint32_t Bb = sbase + B_OFF + buf * B_BUF;
        #pragma unroll
        for (int ks = 0; ks < 16; ks++) {
            uint32_t a[2][4], b[4][2];
            int kbyte = ks * 32;
            #pragma unroll
            for (int mf = 0; mf < 2; mf++) {
                uint32_t addr = Ab + (wm * 32 + mf * 16 + a_row_l) * A_ROW + kbyte + a_kh;
                LDSM_X4(a[mf][0], a[mf][1], a[mf][2], a[mf][3], addr);
            }
            #pragma unroll
            for (int np = 0; np < 2; np++) {
                uint32_t addr = Bb + (wn * 32 + np * 16 + b_row_l) * B_ROW + kbyte + b_kh;
                LDSM_X4(b[np*2][0], b[np*2][1], b[np*2+1][0], b[np*2+1][1], addr);
            }
            #pragma unroll
            for (int mf = 0; mf < 2; mf++)
                #pragma unroll
                for (int nf = 0; nf < 4; nf++)
                    MMA_F16(acc[mf][nf], a[mf], b[nf]);
        }

        // epilogue: dist = enorm - 2*dot, update best1/best2
        {
            int n0 = t * 128;
            const float* en = (const float*)(sm + EN_OFF);
            #pragma unroll
            for (int nf = 0; nf < 4; nf++) {
                int cl = wn * 32 + nf * 8 + tig * 2;
                float e0 = en[cl], e1 = en[cl + 1];
                int gc0 = n0 + cl, gc1 = gc0 + 1;
                #pragma unroll
                for (int mf = 0; mf < 2; mf++) {
                    int l0 = mf * 2, l1 = mf * 2 + 1;
                    float d;
                    d = e0 - 2.f * acc[mf][nf][0];
                    if (d < bv[l0]) { b2[l0] = bv[l0]; bv[l0] = d; bi[l0] = gc0; }
                    else if (d < b2[l0]) b2[l0] = d;
                    d = e1 - 2.f * acc[mf][nf][1];
                    if (d < bv[l0]) { b2[l0] = bv[l0]; bv[l0] = d; bi[l0] = gc1; }
                    else if (d < b2[l0]) b2[l0] = d;
                    d = e0 - 2.f * acc[mf][nf][2];
                    if (d < bv[l1]) { b2[l1] = bv[l1]; bv[l1] = d; bi[l1] = gc0; }
                    else if (d < b2[l1]) b2[l1] = d;
                    d = e1 - 2.f * acc[mf][nf][3];
                    if (d < bv[l1]) { b2[l1] = bv[l1]; bv[l1] = d; bi[l1] = gc1; }
                    else if (d < b2[l1]) b2[l1] = d;
                }
            }
        }
    }

    // merge across lanes sharing a row (lane%4 partners: xor 1, xor 2)
    #pragma unroll
    for (int l = 0; l < 4; l++) {
        #pragma unroll
        for (int o = 1; o <= 2; o <<= 1) {
            float ov = __shfl_xor_sync(0xffffffffu, bv[l], o);
            int   oi = __shfl_xor_sync(0xffffffffu, bi[l], o);
            float o2 = __shfl_xor_sync(0xffffffffu, b2[l], o);
            float n2;
            if (ov < bv[l] || (ov == bv[l] && oi < bi[l])) {
                n2 = fminf(bv[l], o2);
                bv[l] = ov; bi[l] = oi;
            } else {
                n2 = fminf(ov, b2[l]);
            }
            b2[l] = fminf(b2[l], n2);
        }
    }
    if (tig == 0) {
        float* rv = (float*)(sm + RV_OFF);
        int*   ri = (int*)(sm + RI_OFF);
        float* r2 = (float*)(sm + R2_OFF);
        #pragma unroll
        for (int l = 0; l < 4; l++) {
            int mf = l >> 1, r = l & 1;
            int row = wm * 32 + mf * 16 + gid + r * 8;
            rv[row * 4 + wn] = bv[l];
            ri[row * 4 + wn] = bi[l];
            r2[row * 4 + wn] = b2[l];
        }
    }
    __syncthreads();
    if (tid < 128) {
        const float* rv = (const float*)(sm + RV_OFF);
        const int*   ri = (const int*)(sm + RI_OFF);
        const float* r2 = (const float*)(sm + R2_OFF);
        float v1 = rv[tid * 4], s2 = r2[tid * 4];
        int i1 = ri[tid * 4];
        #pragma unroll
        for (int w = 1; w < 4; w++) {
            float ov = rv[tid * 4 + w], o2 = r2[tid * 4 + w];
            int oi = ri[tid * 4 + w];
            float n2;
            if (ov < v1 || (ov == v1 && oi < i1)) {
                n2 = fminf(v1, o2); v1 = ov; i1 = oi;
            } else {
                n2 = fminf(ov, s2);
            }
            s2 = fminf(s2, n2);
        }
        g_idx[m0 + tid] = i1;
        int f = (s2 - v1 < TAU) ? 1 : 0;
        g_fix[m0 + tid] = f;
        if (f) {
            int s = atomicAdd(&g_nfix, 1);
            g_fixlist[s] = m0 + tid;
        }
    }
}

// ======== tiled exact fp32 re-argmin over compacted fixup rows =============
// Unit = (group of 16 rows) x (1024-code octant). CTA-local reduce, then one
// packed atomicMin(u64) per row per unit.
__global__ __launch_bounds__(256)
void k_fixup(const float* __restrict__ z, const float* __restrict__ emb) {
    __shared__ float zs[16][260];
    __shared__ unsigned long long red[16][8];
    __shared__ int rows_s[16];
    int n = g_nfix;
    int nunits = ((n + 15) >> 4) << 3;   // ngroups * 8
    int lane = threadIdx.x & 31, wid = threadIdx.x >> 5;
    for (int u = blockIdx.x; u < nunits; u += gridDim.x) {
        int g = u >> 3, oct = u & 7;
        int base = g << 4;
        int cnt = min(16, n - base);
        __syncthreads();   // protect smem reuse across units
        if (threadIdx.x < 16)
            rows_s[threadIdx.x] = (threadIdx.x < cnt) ? g_fixlist[base + threadIdx.x] : 0;
        __syncthreads();
        for (int i = threadIdx.x; i < 16 * 256; i += 256) {
            int r = i >> 8, d = i & 255;
            zs[r][d] = (r < cnt) ? z[(size_t)rows_s[r] * ND + d] : 0.f;
        }
        __syncthreads();
        unsigned long long best[16];
        #pragma unroll
        for (int r = 0; r < 16; r++) best[r] = ~0ull;
        for (int cc = 0; cc < 4; cc++) {
            int k = (oct << 10) + (cc << 8) + threadIdx.x;
            const float4* ep = (const float4*)(emb + (size_t)k * ND);
            float acc[16];
            #pragma unroll
            for (int r = 0; r < 16; r++) acc[r] = 0.f;
            #pragma unroll 8
            for (int q = 0; q < 64; q++) {
                float4 e = ep[q];
                #pragma unroll
                for (int r = 0; r < 16; r++)
                    acc[r] += e.x * zs[r][q*4+0] + e.y * zs[r][q*4+1]
                            + e.z * zs[r][q*4+2] + e.w * zs[r][q*4+3];
            }
            float en = g_enorm[k];
            #pragma unroll
            for (int r = 0; r < 16; r++) {
                unsigned long long key = pack_key(en - 2.f * acc[r], k);
                if (key < best[r]) best[r] = key;
            }
        }
        #pragma unroll
        for (int r = 0; r < 16; r++) {
            unsigned long long b = best[r];
            #pragma unroll
            for (int o = 16; o > 0; o >>= 1) {
                unsigned long long ob = __shfl_xor_sync(0xffffffffu, b, o);
                if (ob < b) b = ob;
            }
            if (lane == 0) red[r][wid] = b;
        }
        __syncthreads();
        if (threadIdx.x < 16 && threadIdx.x < cnt) {
            unsigned long long m = red[threadIdx.x][0];
            #pragma unroll
            for (int w = 1; w < 8; w++)
                if (red[threadIdx.x][w] < m) m = red[threadIdx.x][w];
            atomicMin(&g_best[rows_s[threadIdx.x]], m);
        }
    }
}

__global__ void k_fixapply() {
    int b = blockIdx.x * 256 + threadIdx.x;
    if (g_fix[b]) g_idx[b] = (int)(g_best[b] & 0xFFFFFFFFull);
}

// ========================= post-argmin kernels =============================
__global__ void k_scatter(const float* __restrict__ z,
                          const float* __restrict__ emb,
                          float* __restrict__ out) {
    __shared__ float ls[8];
    int warp = threadIdx.x >> 5, lane = threadIdx.x & 31;
    int b = blockIdx.x * 8 + warp;
    int idx = g_idx[b];
    const float4* zp = (const float4*)(z + (size_t)b * ND);
    const float4* ep = (const float4*)(emb + (size_t)idx * ND);
    float4* oq = (float4*)(out + O_ZQ + (size_t)b * ND);
    float* esum = g_esum + (size_t)idx * ND;
    float lsum = 0.f;
    #pragma unroll
    for (int j = lane; j < ND / 4; j += 32) {
        float4 zv = zp[j], ev = ep[j];
        oq[j] = ev;
        float dx = ev.x - zv.x, dy = ev.y - zv.y, dz = ev.z - zv.z, dw = ev.w - zv.w;
        lsum += dx * dx + dy * dy + dz * dz + dw * dw;
        atomicAdd(&esum[j * 4 + 0], zv.x);
        atomicAdd(&esum[j * 4 + 1], zv.y);
        atomicAdd(&esum[j * 4 + 2], zv.z);
        atomicAdd(&esum[j * 4 + 3], zv.w);
    }
    #pragma unroll
    for (int o = 16; o > 0; o >>= 1) lsum += __shfl_xor_sync(0xffffffffu, lsum, o);
    if (lane == 0) {
        ls[warp] = lsum;
        atomicAdd(&g_cs[idx], 1.f);
        out[O_IDX + b] = (float)idx;
    }
    __syncthreads();
    if (threadIdx.x == 0) {
        float s = 0.f;
        #pragma unroll
        for (int w = 0; w < 8; w++) s += ls[w];
        atomicAdd(&g_loss, s);
    }
}

__global__ void k_ema(const float* __restrict__ ema_cs) {
    __shared__ float sn[8], sp[8];
    int k = blockIdx.x * 256 + threadIdx.x;
    float cs = g_cs[k];
    float ncs = DECAY * ema_cs[k] + (1.f - DECAY) * cs;
    g_newcs[k] = ncs;
    float p = cs * (1.f / NB);
    float t = p * logf(p + 1e-10f);
    #pragma unroll
    for (int o = 16; o > 0; o >>= 1) {
        ncs += __shfl_xor_sync(0xffffffffu, ncs, o);
        t   += __shfl_xor_sync(0xffffffffu, t, o);
    }
    int warp = threadIdx.x >> 5, lane = threadIdx.x & 31;
    if (lane == 0) { sn[warp] = ncs; sp[warp] = t; }
    __syncthreads();
    if (threadIdx.x == 0) {
        float a = 0.f, b = 0.f;
        #pragma unroll
        for (int w = 0; w < 8; w++) { a += sn[w]; b += sp[w]; }
        atomicAdd(&g_n, a);
        atomicAdd(&g_plx, b);
    }
}

__global__ void k_final(const float* __restrict__ z,
                        const float* __restrict__ ema_es,
                        const float* __restrict__ noise,
                        const int* __restrict__ reinit_idx,
                        float* __restrict__ out) {
    int k = blockIdx.x * 4 + (threadIdx.x >> 6);
    int dq = threadIdx.x & 63;
    float n = g_n;
    float ncs = g_newcs[k];
    float cs_sm = (ncs + EPSV) / (n + NK * EPSV) * n;
    bool dead = (ncs / n) < (1.f / NK / 10.f);
    int ridx = reinit_idx[k];

    float4 eo = ((const float4*)(ema_es + (size_t)k * ND))[dq];
    float4 s  = ((const float4*)(g_esum + (size_t)k * ND))[dq];
    float4 nes;
    nes.x = DECAY * eo.x + (1.f - DECAY) * s.x;
    nes.y = DECAY * eo.y + (1.f - DECAY) * s.y;
    nes.z = DECAY * eo.z + (1.f - DECAY) * s.z;
    nes.w = DECAY * eo.w + (1.f - DECAY) * s.w;
    float inv = 1.f / cs_sm;
    float4 nemb = make_float4(nes.x * inv, nes.y * inv, nes.z * inv, nes.w * inv);
    if (dead) {
        float4 zr = ((const float4*)(z + (size_t)ridx * ND))[dq];
        float4 nz = ((const float4*)(noise + (size_t)k * ND))[dq];
        float4 ri = make_float4(zr.x + nz.x, zr.y + nz.y, zr.z + nz.z, zr.w + nz.w);
        nemb = ri; nes = ri;
    }
    float2* oemb = (float2*)(out + O_EMB + (size_t)k * ND) + dq * 2;
    float2* oes  = (float2*)(out + O_ES  + (size_t)k * ND) + dq * 2;
    oemb[0] = make_float2(nemb.x, nemb.y);
    oemb[1] = make_float2(nemb.z, nemb.w);
    oes[0]  = make_float2(nes.x, nes.y);
    oes[1]  = make_float2(nes.z, nes.w);
    if (dq == 0) out[O_CS + k] = dead ? 1.f : ncs;
}

__global__ void k_scalars(float* __restrict__ out) {
    out[O_LOSS] = CCOST * g_loss / ((float)NB * (float)ND);
    out[O_PLX]  = expf(-g_plx);
}

// ---------------------------------------------------------------------------
extern "C" void kernel_launch(void* const* d_in, const int* in_sizes, int n_in,
                              void* d_out, int out_size) {
    const float* z      = (const float*)d_in[0];
    const float* emb    = (const float*)d_in[1];
    const float* ema_cs = (const float*)d_in[2];
    const float* ema_es = (const float*)d_in[3];
    const float* noise  = (const float*)d_in[4];
    const int*   ridx   = (const int*)d_in[5];
    float* out = (float*)d_out;

    static bool attr_set = false;
    if (!attr_set) {
        cudaFuncSetAttribute(k_argmin_mma,
                             cudaFuncAttributeMaxDynamicSharedMemorySize, SMEM_MMA);
        attr_set = true;
    }

    k_zero<<<1024, 256>>>();
    k_split<<<(NK * ND) / (256 * 4), 256>>>(emb);
    k_enorm<<<NK / 8, 256>>>(emb);
    k_argmin_mma<<<NB / 128, 512, SMEM_MMA>>>(z);
    k_fixup<<<256, 256>>>(z, emb);
    k_fixapply<<<NB / 256, 256>>>();
    k_scatter<<<NB / 8, 256>>>(z, emb, out);
    k_ema<<<NK / 256, 256>>>(ema_cs);
    k_final<<<NK / 4, 256>>>(z, ema_es, noise, ridx, out);
    k_scalars<<<1, 1>>>(out);
}

// round 16
// speedup vs baseline: 5.2373x; 1.0370x over previous
#include <cuda_runtime.h>
#include <cuda_fp16.h>
#include <math.h>
#include <float.h>
#include <stdint.h>

// Problem sizes
constexpr int NB = 32768;
constexpr int ND = 256;
constexpr int NK = 8192;
constexpr float DECAY = 0.99f;
constexpr float EPSV  = 1e-5f;
constexpr float CCOST = 0.25f;
constexpr float TAU   = 0.15f;   // argmin gap threshold for fp32 fixup

// Output layout (flattened reference tuple, float32)
constexpr size_t O_ZQ   = 0;
constexpr size_t O_LOSS = (size_t)NB * ND;            // 8388608
constexpr size_t O_IDX  = O_LOSS + 1;
constexpr size_t O_PLX  = O_IDX + NB;
constexpr size_t O_EMB  = O_PLX + 1;                  // 8B aligned only!
constexpr size_t O_CS   = O_EMB + (size_t)NK * ND;
constexpr size_t O_ES   = O_CS + NK;                  // 8B aligned only!

// Scratch (device globals — no allocation). All scratch is self-resetting:
// every consumer restores its input to the state the next graph replay needs.
__device__ float g_enorm[NK];
__device__ int   g_idx[NB];
__device__ int   g_fix[NB];
__device__ int   g_fixlist[NB];
__device__ int   g_nfix;                       // starts 0; reset by k_scatter
__device__ unsigned long long g_best[NB];      // seeded ~0ull by argmin when flagged
__device__ float g_cs[NK];                     // starts 0; reset by k_ema
__device__ float g_esum[(size_t)NK * ND];      // starts 0; reset by k_final
__device__ float g_newcs[NK];
__device__ float g_loss;                       // starts 0; reset by k_scalars
__device__ float g_n;
__device__ float g_plx;
__device__ __half g_eh[(size_t)NK * ND];

// ============================ PTX helpers ==================================
__device__ __forceinline__ uint32_t smem_to_u32(const void* p) {
    uint32_t a;
    asm("{ .reg .u64 t; cvta.to.shared.u64 t, %1; cvt.u32.u64 %0, t; }"
        : "=r"(a) : "l"(p));
    return a;
}
__device__ __forceinline__ void cp_async16(uint32_t dst, const void* src) {
    asm volatile("cp.async.cg.shared.global [%0], [%1], 16;"
        :: "r"(dst), "l"(src) : "memory");
}
#define CP_COMMIT() asm volatile("cp.async.commit_group;" ::: "memory")
#define CP_WAIT_1() asm volatile("cp.async.wait_group 1;" ::: "memory")
#define CP_WAIT_0() asm volatile("cp.async.wait_group 0;" ::: "memory")

#define MMA_F16(c, a, b) \
    asm volatile("mma.sync.aligned.m16n8k16.row.col.f32.f16.f16.f32 " \
        "{%0,%1,%2,%3}, {%4,%5,%6,%7}, {%8,%9}, {%0,%1,%2,%3};" \
        : "+f"((c)[0]), "+f"((c)[1]), "+f"((c)[2]), "+f"((c)[3]) \
        : "r"((a)[0]), "r"((a)[1]), "r"((a)[2]), "r"((a)[3]), \
          "r"((b)[0]), "r"((b)[1]))

#define LDSM_X4(r0, r1, r2, r3, addr) \
    asm volatile("ldmatrix.sync.aligned.m8n8.x4.shared.b16 {%0,%1,%2,%3}, [%4];" \
        : "=r"(r0), "=r"(r1), "=r"(r2), "=r"(r3) : "r"(addr))

// vectorized no-return global atomic add (PTX ISA 8.1+, sm_90+)
__device__ __forceinline__ void red_add_v4(float* p, float4 v) {
    asm volatile("red.global.add.v4.f32 [%0], {%1,%2,%3,%4};"
        :: "l"(p), "f"(v.x), "f"(v.y), "f"(v.z), "f"(v.w) : "memory");
}

// sortable key for fp32 (any sign) + index tiebreak (lower idx wins)
__device__ __forceinline__ unsigned long long pack_key(float d, int k) {
    uint32_t b = __float_as_uint(d);
    b = (b & 0x80000000u) ? ~b : (b | 0x80000000u);
    return ((unsigned long long)b << 32) | (uint32_t)k;
}

// smem byte layout (k_argmin_mma): fp16 single-pass, full-K tiles
constexpr int A_OFF  = 0;          // A_s[128][264] fp16 (+8 pad)
constexpr int A_ROW  = 528;
constexpr int B_OFF  = 67584;
constexpr int B_BUF  = 67584;      // B_s[128][264] fp16 per buffer
constexpr int B_ROW  = 528;
constexpr int EN_OFF = B_OFF + 2 * B_BUF;   // float[128]
constexpr int RV_OFF = EN_OFF + 512;
constexpr int RI_OFF = RV_OFF + 2048;
constexpr int R2_OFF = RI_OFF + 2048;
constexpr int SMEM_MMA = R2_OFF + 2048;     // 209408

// ================= fused prep: emb -> fp16 codebook + norms ================
// One warp per code: convert row to fp16 (g_eh) and compute e-norm (g_enorm).
__global__ void k_prep(const float* __restrict__ emb) {
    int warp = threadIdx.x >> 5, lane = threadIdx.x & 31;
    int k = blockIdx.x * 8 + warp;
    const float4* ep = (const float4*)(emb + (size_t)k * ND) + lane * 2;
    float4 a = ep[0], b = ep[1];
    // fp16 store (16B per lane)
    __half2 h0 = __floats2half2_rn(a.x, a.y);
    __half2 h1 = __floats2half2_rn(a.z, a.w);
    __half2 h2 = __floats2half2_rn(b.x, b.y);
    __half2 h3 = __floats2half2_rn(b.z, b.w);
    uint4 hp;
    hp.x = *(uint32_t*)&h0; hp.y = *(uint32_t*)&h1;
    hp.z = *(uint32_t*)&h2; hp.w = *(uint32_t*)&h3;
    *(uint4*)(g_eh + (size_t)k * ND + lane * 8) = hp;
    // norm
    float s = a.x*a.x + a.y*a.y + a.z*a.z + a.w*a.w
            + b.x*b.x + b.y*b.y + b.z*b.z + b.w*b.w;
    #pragma unroll
    for (int o = 16; o > 0; o >>= 1) s += __shfl_xor_sync(0xffffffffu, s, o);
    if (lane == 0) g_enorm[k] = s;
}

// ===================== fp16 mma.sync fused distance+argmin =================
__global__ __launch_bounds__(512, 1)
void k_argmin_mma(const float* __restrict__ z) {
    extern __shared__ char sm[];
    const uint32_t sbase = smem_to_u32(sm);
    const int tid = threadIdx.x;
    const int lane = tid & 31, warp = tid >> 5;
    const int wm = warp & 3, wn = warp >> 2;
    const int gid = lane >> 2, tig = lane & 3;
    const int m0 = blockIdx.x * 128;

    auto issue_tile = [&](int t) {
        const __half* src = g_eh + (size_t)(t * 128) * ND;
        uint32_t dbase = sbase + B_OFF + (t & 1) * B_BUF;
        #pragma unroll
        for (int i = 0; i < 8; i++) {
            int th = tid + i * 512;
            int row = th >> 5, c16 = th & 31;
            cp_async16(dbase + row * B_ROW + c16 * 16,
                       src + (size_t)row * ND + c16 * 8);
        }
        CP_COMMIT();
    };

    issue_tile(0);

    // A resident: convert z rows to fp16 in smem
    #pragma unroll 4
    for (int j = 0; j < 16; j++) {
        int gi = tid + j * 512;
        int row = gi >> 6, q = gi & 63;
        float4 v = ((const float4*)(z + (size_t)(m0 + row) * ND))[q];
        __half2 h01 = __floats2half2_rn(v.x, v.y);
        __half2 h23 = __floats2half2_rn(v.z, v.w);
        uint2 hp;
        hp.x = *(uint32_t*)&h01;
        hp.y = *(uint32_t*)&h23;
        *(uint2*)(sm + A_OFF + row * A_ROW + q * 8) = hp;
    }

    float bv[4], b2[4];
    int bi[4];
    #pragma unroll
    for (int i = 0; i < 4; i++) { bv[i] = FLT_MAX; b2[i] = FLT_MAX; bi[i] = 0x7fffffff; }

    const int a_row_l = (lane & 15);
    const int a_kh    = (lane >> 4) * 16;
    const int b_row_l = (lane & 7) + ((lane >> 4) & 1) * 8;
    const int b_kh    = ((lane >> 3) & 1) * 16;

    for (int t = 0; t < 64; t++) {
        int buf = t & 1;
        __syncthreads();
        if (tid < 128)
            ((float*)(sm + EN_OFF))[tid] = g_enorm[t * 128 + tid];
        if (t + 1 < 64) { issue_tile(t + 1); CP_WAIT_1(); }
        else            { CP_WAIT_0(); }
        __syncthreads();

        float acc[2][4][4];
        #pragma unroll
        for (int mf = 0; mf < 2; mf++)
            #pragma unroll
            for (int nf = 0; nf < 4; nf++)
                #pragma unroll
                for (int r = 0; r < 4; r++) acc[mf][nf][r] = 0.f;

        uint32_t Ab = sbase + A_OFF;
        uint32_t Bb = sbase + B_OFF + buf * B_BUF;
        #pragma unroll
        for (int ks = 0; ks < 16; ks++) {
            uint32_t a[2][4], b[4][2];
            int kbyte = ks * 32;
            #pragma unroll
            for (int mf = 0; mf < 2; mf++) {
                uint32_t addr = Ab + (wm * 32 + mf * 16 + a_row_l) * A_ROW + kbyte + a_kh;
                LDSM_X4(a[mf][0], a[mf][1], a[mf][2], a[mf][3], addr);
            }
            #pragma unroll
            for (int np = 0; np < 2; np++) {
                uint32_t addr = Bb + (wn * 32 + np * 16 + b_row_l) * B_ROW + kbyte + b_kh;
                LDSM_X4(b[np*2][0], b[np*2][1], b[np*2+1][0], b[np*2+1][1], addr);
            }
            #pragma unroll
            for (int mf = 0; mf < 2; mf++)
                #pragma unroll
                for (int nf = 0; nf < 4; nf++)
                    MMA_F16(acc[mf][nf], a[mf], b[nf]);
        }

        {
            int n0 = t * 128;
            const float* en = (const float*)(sm + EN_OFF);
            #pragma unroll
            for (int nf = 0; nf < 4; nf++) {
                int cl = wn * 32 + nf * 8 + tig * 2;
                float e0 = en[cl], e1 = en[cl + 1];
                int gc0 = n0 + cl, gc1 = gc0 + 1;
                #pragma unroll
                for (int mf = 0; mf < 2; mf++) {
                    int l0 = mf * 2, l1 = mf * 2 + 1;
                    float d;
                    d = e0 - 2.f * acc[mf][nf][0];
                    if (d < bv[l0]) { b2[l0] = bv[l0]; bv[l0] = d; bi[l0] = gc0; }
                    else if (d < b2[l0]) b2[l0] = d;
                    d = e1 - 2.f * acc[mf][nf][1];
                    if (d < bv[l0]) { b2[l0] = bv[l0]; bv[l0] = d; bi[l0] = gc1; }
                    else if (d < b2[l0]) b2[l0] = d;
                    d = e0 - 2.f * acc[mf][nf][2];
                    if (d < bv[l1]) { b2[l1] = bv[l1]; bv[l1] = d; bi[l1] = gc0; }
                    else if (d < b2[l1]) b2[l1] = d;
                    d = e1 - 2.f * acc[mf][nf][3];
                    if (d < bv[l1]) { b2[l1] = bv[l1]; bv[l1] = d; bi[l1] = gc1; }
                    else if (d < b2[l1]) b2[l1] = d;
                }
            }
        }
    }

    // merge across lanes sharing a row (lane%4 partners: xor 1, xor 2)
    #pragma unroll
    for (int l = 0; l < 4; l++) {
        #pragma unroll
        for (int o = 1; o <= 2; o <<= 1) {
            float ov = __shfl_xor_sync(0xffffffffu, bv[l], o);
            int   oi = __shfl_xor_sync(0xffffffffu, bi[l], o);
            float o2 = __shfl_xor_sync(0xffffffffu, b2[l], o);
            float n2;
            if (ov < bv[l] || (ov == bv[l] && oi < bi[l])) {
                n2 = fminf(bv[l], o2);
                bv[l] = ov; bi[l] = oi;
            } else {
                n2 = fminf(ov, b2[l]);
            }
            b2[l] = fminf(b2[l], n2);
        }
    }
    if (tig == 0) {
        float* rv = (float*)(sm + RV_OFF);
        int*   ri = (int*)(sm + RI_OFF);
        float* r2 = (float*)(sm + R2_OFF);
        #pragma unroll
        for (int l = 0; l < 4; l++) {
            int mf = l >> 1, r = l & 1;
            int row = wm * 32 + mf * 16 + gid + r * 8;
            rv[row * 4 + wn] = bv[l];
            ri[row * 4 + wn] = bi[l];
            r2[row * 4 + wn] = b2[l];
        }
    }
    __syncthreads();
    if (tid < 128) {
        const float* rv = (const float*)(sm + RV_OFF);
        const int*   ri = (const int*)(sm + RI_OFF);
        const float* r2 = (const float*)(sm + R2_OFF);
        float v1 = rv[tid * 4], s2 = r2[tid * 4];
        int i1 = ri[tid * 4];
        #pragma unroll
        for (int w = 1; w < 4; w++) {
            float ov = rv[tid * 4 + w], o2 = r2[tid * 4 + w];
            int oi = ri[tid * 4 + w];
            float n2;
            if (ov < v1 || (ov == v1 && oi < i1)) {
                n2 = fminf(v1, o2); v1 = ov; i1 = oi;
            } else {
                n2 = fminf(ov, s2);
            }
            s2 = fminf(s2, n2);
        }
        g_idx[m0 + tid] = i1;
        int f = (s2 - v1 < TAU) ? 1 : 0;
        g_fix[m0 + tid] = f;
        if (f) {
            g_best[m0 + tid] = ~0ull;   // seed for atomicMin (replaces k_zero)
            int s = atomicAdd(&g_nfix, 1);
            g_fixlist[s] = m0 + tid;
        }
    }
}

// ======== tiled exact fp32 re-argmin over compacted fixup rows =============
__global__ __launch_bounds__(256)
void k_fixup(const float* __restrict__ z, const float* __restrict__ emb) {
    __shared__ float zs[16][260];
    __shared__ unsigned long long red[16][8];
    __shared__ int rows_s[16];
    int n = g_nfix;
    int nunits = ((n + 15) >> 4) << 3;
    int lane = threadIdx.x & 31, wid = threadIdx.x >> 5;
    for (int u = blockIdx.x; u < nunits; u += gridDim.x) {
        int g = u >> 3, oct = u & 7;
        int base = g << 4;
        int cnt = min(16, n - base);
        __syncthreads();
        if (threadIdx.x < 16)
            rows_s[threadIdx.x] = (threadIdx.x < cnt) ? g_fixlist[base + threadIdx.x] : 0;
        __syncthreads();
        for (int i = threadIdx.x; i < 16 * 256; i += 256) {
            int r = i >> 8, d = i & 255;
            zs[r][d] = (r < cnt) ? z[(size_t)rows_s[r] * ND + d] : 0.f;
        }
        __syncthreads();
        unsigned long long best[16];
        #pragma unroll
        for (int r = 0; r < 16; r++) best[r] = ~0ull;
        for (int cc = 0; cc < 4; cc++) {
            int k = (oct << 10) + (cc << 8) + threadIdx.x;
            const float4* ep = (const float4*)(emb + (size_t)k * ND);
            float acc[16];
            #pragma unroll
            for (int r = 0; r < 16; r++) acc[r] = 0.f;
            #pragma unroll 8
            for (int q = 0; q < 64; q++) {
                float4 e = ep[q];
                #pragma unroll
                for (int r = 0; r < 16; r++)
                    acc[r] += e.x * zs[r][q*4+0] + e.y * zs[r][q*4+1]
                            + e.z * zs[r][q*4+2] + e.w * zs[r][q*4+3];
            }
            float en = g_enorm[k];
            #pragma unroll
            for (int r = 0; r < 16; r++) {
                unsigned long long key = pack_key(en - 2.f * acc[r], k);
                if (key < best[r]) best[r] = key;
            }
        }
        #pragma unroll
        for (int r = 0; r < 16; r++) {
            unsigned long long b = best[r];
            #pragma unroll
            for (int o = 16; o > 0; o >>= 1) {
                unsigned long long ob = __shfl_xor_sync(0xffffffffu, b, o);
                if (ob < b) b = ob;
            }
            if (lane == 0) red[r][wid] = b;
        }
        __syncthreads();
        if (threadIdx.x < 16 && threadIdx.x < cnt) {
            unsigned long long m = red[threadIdx.x][0];
            #pragma unroll
            for (int w = 1; w < 8; w++)
                if (red[threadIdx.x][w] < m) m = red[threadIdx.x][w];
            atomicMin(&g_best[rows_s[threadIdx.x]], m);
        }
    }
}

// ========================= post-argmin kernels =============================
// k_scatter: applies fixup result inline, gathers z_q, accumulates loss,
// cluster counts, and the esum scatter (vectorized red.v4). Resets g_nfix.
__global__ void k_scatter(const float* __restrict__ z,
                          const float* __restrict__ emb,
                          float* __restrict__ out) {
    __shared__ float ls[8];
    int warp = threadIdx.x >> 5, lane = threadIdx.x & 31;
    int b = blockIdx.x * 8 + warp;
    int idx = g_idx[b];
    if (g_fix[b]) idx = (int)(g_best[b] & 0xFFFFFFFFull);
    const float4* zp = (const float4*)(z + (size_t)b * ND);
    const float4* ep = (const float4*)(emb + (size_t)idx * ND);
    float4* oq = (float4*)(out + O_ZQ + (size_t)b * ND);
    float* esum = g_esum + (size_t)idx * ND;
    float lsum = 0.f;
    #pragma unroll
    for (int j = lane; j < ND / 4; j += 32) {
        float4 zv = zp[j], ev = ep[j];
        oq[j] = ev;
        float dx = ev.x - zv.x, dy = ev.y - zv.y, dz = ev.z - zv.z, dw = ev.w - zv.w;
        lsum += dx * dx + dy * dy + dz * dz + dw * dw;
        red_add_v4(&esum[j * 4], zv);
    }
    #pragma unroll
    for (int o = 16; o > 0; o >>= 1) lsum += __shfl_xor_sync(0xffffffffu, lsum, o);
    if (lane == 0) {
        ls[warp] = lsum;
        atomicAdd(&g_cs[idx], 1.f);
        out[O_IDX + b] = (float)idx;
        g_idx[b] = idx;   // store corrected index for any later consumer
    }
    __syncthreads();
    if (threadIdx.x == 0) {
        float s = 0.f;
        #pragma unroll
        for (int w = 0; w < 8; w++) s += ls[w];
        atomicAdd(&g_loss, s);
        if (blockIdx.x == 0) g_nfix = 0;   // reset for next replay
    }
}

// k_ema: EMA cluster sizes + n + perplexity accum. Resets g_cs.
__global__ void k_ema(const float* __restrict__ ema_cs) {
    __shared__ float sn[8], sp[8];
    int k = blockIdx.x * 256 + threadIdx.x;
    float cs = g_cs[k];
    g_cs[k] = 0.f;                         // reset for next replay
    float ncs = DECAY * ema_cs[k] + (1.f - DECAY) * cs;
    g_newcs[k] = ncs;
    float p = cs * (1.f / NB);
    float t = p * logf(p + 1e-10f);
    #pragma unroll
    for (int o = 16; o > 0; o >>= 1) {
        ncs += __shfl_xor_sync(0xffffffffu, ncs, o);
        t   += __shfl_xor_sync(0xffffffffu, t, o);
    }
    int warp = threadIdx.x >> 5, lane = threadIdx.x & 31;
    if (lane == 0) { sn[warp] = ncs; sp[warp] = t; }
    __syncthreads();
    if (threadIdx.x == 0) {
        float a = 0.f, b = 0.f;
        #pragma unroll
        for (int w = 0; w < 8; w++) { a += sn[w]; b += sp[w]; }
        atomicAdd(&g_n, a);
        atomicAdd(&g_plx, b);
    }
}

// k_final: codebook update + dead reinit. Resets g_esum.
__global__ void k_final(const float* __restrict__ z,
                        const float* __restrict__ ema_es,
                        const float* __restrict__ noise,
                        const int* __restrict__ reinit_idx,
                        float* __restrict__ out) {
    int k = blockIdx.x * 4 + (threadIdx.x >> 6);
    int dq = threadIdx.x & 63;
    float n = g_n;
    float ncs = g_newcs[k];
    float cs_sm = (ncs + EPSV) / (n + NK * EPSV) * n;
    bool dead = (ncs / n) < (1.f / NK / 10.f);
    int ridx = reinit_idx[k];

    float4 eo = ((const float4*)(ema_es + (size_t)k * ND))[dq];
    float4 s  = ((const float4*)(g_esum + (size_t)k * ND))[dq];
    ((float4*)(g_esum + (size_t)k * ND))[dq] = make_float4(0.f, 0.f, 0.f, 0.f);
    float4 nes;
    nes.x = DECAY * eo.x + (1.f - DECAY) * s.x;
    nes.y = DECAY * eo.y + (1.f - DECAY) * s.y;
    nes.z = DECAY * eo.z + (1.f - DECAY) * s.z;
    nes.w = DECAY * eo.w + (1.f - DECAY) * s.w;
    float inv = 1.f / cs_sm;
    float4 nemb = make_float4(nes.x * inv, nes.y * inv, nes.z * inv, nes.w * inv);
    if (dead) {
        float4 zr = ((const float4*)(z + (size_t)ridx * ND))[dq];
        float4 nz = ((const float4*)(noise + (size_t)k * ND))[dq];
        float4 ri = make_float4(zr.x + nz.x, zr.y + nz.y, zr.z + nz.z, zr.w + nz.w);
        nemb = ri; nes = ri;
    }
    float2* oemb = (float2*)(out + O_EMB + (size_t)k * ND) + dq * 2;
    float2* oes  = (float2*)(out + O_ES  + (size_t)k * ND) + dq * 2;
    oemb[0] = make_float2(nemb.x, nemb.y);
    oemb[1] = make_float2(nemb.z, nemb.w);
    oes[0]  = make_float2(nes.x, nes.y);
    oes[1]  = make_float2(nes.z, nes.w);
    if (dq == 0) out[O_CS + k] = dead ? 1.f : ncs;
}

// k_scalars: final scalars; resets scalar accumulators for next replay.
__global__ void k_scalars(float* __restrict__ out) {
    out[O_LOSS] = CCOST * g_loss / ((float)NB * (float)ND);
    out[O_PLX]  = expf(-g_plx);
    g_loss = 0.f; g_n = 0.f; g_plx = 0.f;
}

// ---------------------------------------------------------------------------
extern "C" void kernel_launch(void* const* d_in, const int* in_sizes, int n_in,
                              void* d_out, int out_size) {
    const float* z      = (const float*)d_in[0];
    const float* emb    = (const float*)d_in[1];
    const float* ema_cs = (const float*)d_in[2];
    const float* ema_es = (const float*)d_in[3];
    const float* noise  = (const float*)d_in[4];
    const int*   ridx   = (const int*)d_in[5];
    float* out = (float*)d_out;

    static bool attr_set = false;
    if (!attr_set) {
        cudaFuncSetAttribute(k_argmin_mma,
                             cudaFuncAttributeMaxDynamicSharedMemorySize, SMEM_MMA);
        attr_set = true;
    }

    k_prep<<<NK / 8, 256>>>(emb);
    k_argmin_mma<<<NB / 128, 512, SMEM_MMA>>>(z);
    k_fixup<<<256, 256>>>(z, emb);
    k_scatter<<<NB / 8, 256>>>(z, emb, out);
    k_ema<<<NK / 256, 256>>>(ema_cs);
    k_final<<<NK / 4, 256>>>(z, ema_es, noise, ridx, out);
    k_scalars<<<1, 1>>>(out);
}